// round 11
// baseline (speedup 1.0000x reference)
#include <cuda_runtime.h>
#include <math.h>
#include <float.h>

typedef unsigned long long u64;
#define FULLMASK 0xFFFFFFFFu

// ---------- scratch (no allocations allowed) ----------
__device__ __align__(16) float g_Q1[1024*128];
__device__ __align__(16) float g_V1[1024*128];
__device__ __align__(16) float g_O1[1024*128];
__device__ __align__(16) float g_K4[1024*128];
__device__ __align__(16) float g_V4[1024*128];
__device__ __align__(16) float g_Q4[16*128];
__device__ __align__(16) float g_O4[16384*128];

// ---------- f32x2 packed math ----------
__device__ __forceinline__ u64 pk2(float lo, float hi){
    u64 r; asm("mov.b64 %0, {%1,%2};" : "=l"(r) : "f"(lo), "f"(hi)); return r;
}
__device__ __forceinline__ void upk2(u64 v, float& lo, float& hi){
    asm("mov.b64 {%0,%1}, %2;" : "=f"(lo), "=f"(hi) : "l"(v));
}
__device__ __forceinline__ void fma2(u64& d, u64 a, u64 b){
    asm("fma.rn.f32x2 %0, %1, %2, %0;" : "+l"(d) : "l"(a), "l"(b));
}

// ---------- helpers ----------
__device__ __forceinline__ float warpMax(float v){
    #pragma unroll
    for (int o = 16; o; o >>= 1) v = fmaxf(v, __shfl_xor_sync(FULLMASK, v, o));
    return v;
}
__device__ __forceinline__ float warpSum(float v){
    #pragma unroll
    for (int o = 16; o; o >>= 1) v += __shfl_xor_sync(FULLMASK, v, o);
    return v;
}
__device__ __forceinline__ float warpInclScan(float x, int lane){
    #pragma unroll
    for (int o = 1; o < 32; o <<= 1) {
        float y = __shfl_up_sync(FULLMASK, x, o);
        if (lane >= o) x += y;
    }
    return x;
}
__device__ __forceinline__ float fast_sqrt(float x){
    float r; asm("sqrt.approx.f32 %0, %1;" : "=f"(r) : "f"(x)); return r;
}
__device__ __forceinline__ float dot16(const float4 a0, const float4 a1, const float4 a2, const float4 a3,
                                       const float4 b0, const float4 b1, const float4 b2, const float4 b3){
    float s;
    s  = a0.x*b0.x + a0.y*b0.y + a0.z*b0.z + a0.w*b0.w;
    s += a1.x*b1.x + a1.y*b1.y + a1.z*b1.z + a1.w*b1.w;
    s += a2.x*b2.x + a2.y*b2.y + a2.z*b2.z + a2.w*b2.w;
    s += a3.x*b3.x + a3.y*b3.y + a3.z*b3.z + a3.w*b3.w;
    return s;
}
// Reduce 16 accumulators across 32 lanes; lane l gets sum over lanes of r[l&15].
__device__ __forceinline__ float foldReduce16(float r[16], int lane){
    #pragma unroll
    for (int d = 0; d < 16; d++) r[d] += __shfl_xor_sync(FULLMASK, r[d], 16);
    #pragma unroll
    for (int d = 0; d < 8; d++) {
        float x = (lane & 8) ? r[d] : r[d+8];
        float y = __shfl_xor_sync(FULLMASK, x, 8);
        r[d] = ((lane & 8) ? r[d+8] : r[d]) + y;
    }
    #pragma unroll
    for (int d = 0; d < 4; d++) {
        float x = (lane & 4) ? r[d] : r[d+4];
        float y = __shfl_xor_sync(FULLMASK, x, 4);
        r[d] = ((lane & 4) ? r[d+4] : r[d]) + y;
    }
    #pragma unroll
    for (int d = 0; d < 2; d++) {
        float x = (lane & 2) ? r[d] : r[d+2];
        float y = __shfl_xor_sync(FULLMASK, x, 2);
        r[d] = ((lane & 2) ? r[d+2] : r[d]) + y;
    }
    float x = (lane & 1) ? r[0] : r[1];
    float y = __shfl_xor_sync(FULLMASK, x, 1);
    return ((lane & 1) ? r[1] : r[0]) + y;
}

// ---------- GEMM core: out[row0..row0+31][0..127] = X@W^T + bias (f32x2) ----------
__device__ __forceinline__ void gemm_core(const float* __restrict__ X, const float* __restrict__ W,
                                          const float* __restrict__ bias, float* __restrict__ out,
                                          int M, int row0, float* Wt, float* Xs){
    int tid = threadIdx.x, tx = tid & 31, ty = tid >> 5;
    u64 acc[4][2];
    #pragma unroll
    for (int q = 0; q < 4; q++){ acc[q][0] = 0ull; acc[q][1] = 0ull; }

    for (int k0 = 0; k0 < 128; k0 += 32) {
        #pragma unroll
        for (int iL = 0; iL < 16; iL++) {
            int idx = tid + 256*iL;
            int c = idx >> 5, kk = idx & 31;
            Wt[kk*132 + c] = W[c*128 + k0 + kk];
        }
        #pragma unroll
        for (int iL = 0; iL < 4; iL++) {
            int idx = tid + 256*iL;
            int r = idx >> 5, kk = idx & 31;
            int grow = row0 + r;
            Xs[r*33 + kk] = (grow < M) ? X[(size_t)grow*128 + k0 + kk] : 0.f;
        }
        __syncthreads();
        #pragma unroll
        for (int kk = 0; kk < 32; kk++) {
            ulonglong2 wv = *(const ulonglong2*)&Wt[kk*132 + tx*4];
            #pragma unroll
            for (int q = 0; q < 4; q++) {
                float xv = Xs[(ty + 8*q)*33 + kk];
                u64 xx = pk2(xv, xv);
                fma2(acc[q][0], xx, wv.x);
                fma2(acc[q][1], xx, wv.y);
            }
        }
        __syncthreads();
    }
    float4 bv = *(const float4*)&bias[tx*4];
    #pragma unroll
    for (int q = 0; q < 4; q++) {
        int grow = row0 + ty + 8*q;
        if (grow < M) {
            float4 o;
            upk2(acc[q][0], o.x, o.y);
            upk2(acc[q][1], o.z, o.w);
            o.x += bv.x; o.y += bv.y; o.z += bv.z; o.w += bv.w;
            *(float4*)&out[(size_t)grow*128 + tx*4] = o;
        }
    }
}

// ---------- fused projections: Q1 | V1 | K4 | Q4 in one launch ----------
__global__ __launch_bounds__(256) void proj_kernel(const float* __restrict__ q_emb,
                                                   const float* __restrict__ s_emb,
                                                   const float* __restrict__ know,
                                                   const float* __restrict__ Wq1, const float* __restrict__ bq1,
                                                   const float* __restrict__ Wv1, const float* __restrict__ bv1,
                                                   const float* __restrict__ Wk4, const float* __restrict__ bk4,
                                                   const float* __restrict__ Wq4, const float* __restrict__ bq4){
    __shared__ __align__(16) float Wt[32*132];
    __shared__ float Xs[32*33];
    int bx = blockIdx.x;
    const float *X, *W, *bias; float* out; int M, row0;
    if (bx < 32)      { X=q_emb; W=Wq1; bias=bq1; out=g_Q1; M=1024; row0=bx*32; }
    else if (bx < 64) { X=s_emb; W=Wv1; bias=bv1; out=g_V1; M=1024; row0=(bx-32)*32; }
    else if (bx < 96) { X=q_emb; W=Wk4; bias=bk4; out=g_K4; M=1024; row0=(bx-64)*32; }
    else              { X=know;  W=Wq4; bias=bq4; out=g_Q4; M=16;   row0=0; }
    gemm_core(X, W, bias, out, M, row0, Wt, Xs);
}

// ---------- fused P+V4 (16-row tiles): V4 = LN(O1@Wo + b + q_emb) @ Wv^T + bv ----------
__global__ __launch_bounds__(256) void pv_kernel(const float* __restrict__ q_emb,
                                                 const float* __restrict__ Wo, const float* __restrict__ bo,
                                                 const float* __restrict__ lng, const float* __restrict__ lnb,
                                                 const float* __restrict__ Wv, const float* __restrict__ bv4){
    __shared__ __align__(16) float Wt[32*132];
    __shared__ float Xs[16*33];
    __shared__ __align__(16) float Os[16*132];
    int row0 = blockIdx.x * 16;
    int tid = threadIdx.x, tx = tid & 31, ty = tid >> 5;

    u64 acc[2][2];
    #pragma unroll
    for (int q = 0; q < 2; q++){ acc[q][0] = 0ull; acc[q][1] = 0ull; }
    for (int k0 = 0; k0 < 128; k0 += 32) {
        #pragma unroll
        for (int iL = 0; iL < 16; iL++) {
            int idx = tid + 256*iL;
            int c = idx >> 5, kk = idx & 31;
            Wt[kk*132 + c] = Wo[c*128 + k0 + kk];
        }
        #pragma unroll
        for (int iL = 0; iL < 2; iL++) {
            int idx = tid + 256*iL;
            int r = idx >> 5, kk = idx & 31;
            Xs[r*33 + kk] = g_O1[(size_t)(row0 + r)*128 + k0 + kk];
        }
        __syncthreads();
        #pragma unroll
        for (int kk = 0; kk < 32; kk++) {
            ulonglong2 wv = *(const ulonglong2*)&Wt[kk*132 + tx*4];
            #pragma unroll
            for (int q = 0; q < 2; q++) {
                float xv = Xs[(ty + 8*q)*33 + kk];
                u64 xx = pk2(xv, xv);
                fma2(acc[q][0], xx, wv.x);
                fma2(acc[q][1], xx, wv.y);
            }
        }
        __syncthreads();
    }
    {
        float4 bv = *(const float4*)&bo[tx*4];
        #pragma unroll
        for (int q = 0; q < 2; q++) {
            int r = ty + 8*q;
            float4 rv = *(const float4*)&q_emb[(size_t)(row0 + r)*128 + tx*4];
            float4 o;
            upk2(acc[q][0], o.x, o.y);
            upk2(acc[q][1], o.z, o.w);
            o.x += bv.x + rv.x; o.y += bv.y + rv.y;
            o.z += bv.z + rv.z; o.w += bv.w + rv.w;
            *(float4*)&Os[r*132 + tx*4] = o;
        }
    }
    __syncthreads();
    #pragma unroll
    for (int q = 0; q < 2; q++) {
        int r = ty + 8*q;
        float v[4];
        #pragma unroll
        for (int c4 = 0; c4 < 4; c4++) v[c4] = Os[r*132 + tx + 32*c4];
        float s = v[0] + v[1] + v[2] + v[3];
        s = warpSum(s);
        float mean = s * 0.0078125f;
        float vs = 0.f;
        #pragma unroll
        for (int c4 = 0; c4 < 4; c4++) { float d = v[c4] - mean; vs += d*d; }
        vs = warpSum(vs);
        float rs = rsqrtf(vs * 0.0078125f + 1e-5f);
        #pragma unroll
        for (int c4 = 0; c4 < 4; c4++) {
            int c = tx + 32*c4;
            Os[r*132 + c] = (v[c4] - mean)*rs*lng[c] + lnb[c];
        }
    }
    __syncthreads();

    #pragma unroll
    for (int q = 0; q < 2; q++){ acc[q][0] = 0ull; acc[q][1] = 0ull; }
    for (int k0 = 0; k0 < 128; k0 += 32) {
        #pragma unroll
        for (int iL = 0; iL < 16; iL++) {
            int idx = tid + 256*iL;
            int c = idx >> 5, kk = idx & 31;
            Wt[kk*132 + c] = Wv[c*128 + k0 + kk];
        }
        __syncthreads();
        #pragma unroll
        for (int kk = 0; kk < 32; kk++) {
            ulonglong2 wv = *(const ulonglong2*)&Wt[kk*132 + tx*4];
            #pragma unroll
            for (int q = 0; q < 2; q++) {
                float xv = Os[(ty + 8*q)*132 + k0 + kk];
                u64 xx = pk2(xv, xv);
                fma2(acc[q][0], xx, wv.x);
                fma2(acc[q][1], xx, wv.y);
            }
        }
        __syncthreads();
    }
    {
        float4 bv = *(const float4*)&bv4[tx*4];
        #pragma unroll
        for (int q = 0; q < 2; q++) {
            int grow = row0 + ty + 8*q;
            float4 o;
            upk2(acc[q][0], o.x, o.y);
            upk2(acc[q][1], o.z, o.w);
            o.x += bv.x; o.y += bv.y; o.z += bv.z; o.w += bv.w;
            *(float4*)&g_V4[(size_t)grow*128 + tx*4] = o;
        }
    }
}

// ---------- final z GEMM + LN + scatter ----------
__global__ __launch_bounds__(256) void zgemm_kernel(const float* __restrict__ W,
                                                    const float* __restrict__ bias,
                                                    float* __restrict__ out,
                                                    const float* __restrict__ know,
                                                    const float* __restrict__ lng,
                                                    const float* __restrict__ lnb){
    __shared__ __align__(16) float Wt[32*132];
    __shared__ float Xs[32*33];
    __shared__ __align__(16) float Os[32*132];
    int row0 = blockIdx.x * 32;
    int tid = threadIdx.x, tx = tid & 31, ty = tid >> 5;

    u64 acc[4][2];
    #pragma unroll
    for (int q = 0; q < 4; q++){ acc[q][0] = 0ull; acc[q][1] = 0ull; }
    for (int k0 = 0; k0 < 128; k0 += 32) {
        #pragma unroll
        for (int iL = 0; iL < 16; iL++) {
            int idx = tid + 256*iL;
            int c = idx >> 5, kk = idx & 31;
            Wt[kk*132 + c] = W[c*128 + k0 + kk];
        }
        #pragma unroll
        for (int iL = 0; iL < 4; iL++) {
            int idx = tid + 256*iL;
            int r = idx >> 5, kk = idx & 31;
            Xs[r*33 + kk] = g_O4[(size_t)(row0 + r)*128 + k0 + kk];
        }
        __syncthreads();
        #pragma unroll
        for (int kk = 0; kk < 32; kk++) {
            ulonglong2 wv = *(const ulonglong2*)&Wt[kk*132 + tx*4];
            #pragma unroll
            for (int q = 0; q < 4; q++) {
                float xv = Xs[(ty + 8*q)*33 + kk];
                u64 xx = pk2(xv, xv);
                fma2(acc[q][0], xx, wv.x);
                fma2(acc[q][1], xx, wv.y);
            }
        }
        __syncthreads();
    }
    {
        float4 bv = *(const float4*)&bias[tx*4];
        #pragma unroll
        for (int q = 0; q < 4; q++) {
            int r = ty + 8*q;
            int grow = row0 + r;
            int nn = (grow >> 8) & 15;
            float4 rv = *(const float4*)&know[nn*128 + tx*4];
            float4 o;
            upk2(acc[q][0], o.x, o.y);
            upk2(acc[q][1], o.z, o.w);
            o.x += bv.x + rv.x; o.y += bv.y + rv.y;
            o.z += bv.z + rv.z; o.w += bv.w + rv.w;
            *(float4*)&Os[r*132 + tx*4] = o;
        }
    }
    __syncthreads();
    #pragma unroll
    for (int q = 0; q < 4; q++) {
        int r = ty + 8*q;
        int grow = row0 + r;
        float v[4];
        #pragma unroll
        for (int c4 = 0; c4 < 4; c4++) v[c4] = Os[r*132 + tx + 32*c4];
        float s = v[0] + v[1] + v[2] + v[3];
        s = warpSum(s);
        float mean = s * 0.0078125f;
        float vs = 0.f;
        #pragma unroll
        for (int c4 = 0; c4 < 4; c4++) { float d = v[c4] - mean; vs += d*d; }
        vs = warpSum(vs);
        float rs = rsqrtf(vs * 0.0078125f + 1e-5f);
        int bb = grow >> 12, nn = (grow >> 8) & 15, ii = grow & 255;
        size_t ob = ((size_t)(bb*256 + ii))*2048 + (size_t)nn*128;
        #pragma unroll
        for (int c4 = 0; c4 < 4; c4++) {
            int c = tx + 32*c4;
            out[ob + c] = (v[c4] - mean)*rs*lng[c] + lnb[c];
        }
    }
}

// ---------- block1 attention (causal incl diag, kq_same, no maxout) ----------
__global__ __launch_bounds__(256) void attn1_kernel(const float* __restrict__ gamma,
                                                    float* __restrict__ qs){
    __shared__ float4 Ks[256*5];   // 80B pitch -> conflict-free float4
    __shared__ float4 Vs[256*5];
    int split = blockIdx.x, h = blockIdx.y, b = blockIdx.z;
    int tid = threadIdx.x, lane = tid & 31, w = tid >> 5;

    const float4* qg = (const float4*)(g_Q1 + (size_t)b*32768) + h*4;
    const float4* vg = (const float4*)(g_V1 + (size_t)b*32768) + h*4;
    #pragma unroll
    for (int d4 = 0; d4 < 4; d4++) {
        Ks[tid*5 + d4] = qg[(size_t)tid*32 + d4];
        Vs[tid*5 + d4] = vg[(size_t)tid*32 + d4];
    }
    __syncthreads();
    float ag = fabsf(gamma[h]);

    for (int t = 0; t < 4; t++) {
        int i = split + 8*w + 64*t;       // bijective over 0..255
        int cmax = (i >> 5) + 1;
        float4 q0 = Ks[i*5+0], q1 = Ks[i*5+1], q2 = Ks[i*5+2], q3 = Ks[i*5+3];

        float raw[8], mxv = -FLT_MAX;
        #pragma unroll
        for (int c = 0; c < 8; c++) {
            raw[c] = -FLT_MAX;
            if (c < cmax) {
                int j = lane + 32*c;
                if (j <= i)
                    raw[c] = 0.25f * dot16(q0,q1,q2,q3, Ks[j*5+0],Ks[j*5+1],Ks[j*5+2],Ks[j*5+3]);
                mxv = fmaxf(mxv, raw[c]);
            }
        }
        mxv = warpMax(mxv);

        float pref[8]; float base = 0.f;
        #pragma unroll
        for (int c = 0; c < 8; c++) {
            pref[c] = 0.f;
            if (c < cmax) {
                int j = lane + 32*c;
                float ev = (j <= i) ? __expf(raw[c] - mxv) : 0.f;
                float x = warpInclScan(ev, lane);
                pref[c] = base + x;
                base += __shfl_sync(FULLMASK, x, 31);
            }
        }
        float invT = 1.f / base;

        float M = fmaxf(mxv, 0.f);
        float e2[8], sm = 0.f;
        u64 r2[8];
        #pragma unroll
        for (int d = 0; d < 8; d++) r2[d] = 0ull;
        #pragma unroll
        for (int c = 0; c < 8; c++) {
            e2[c] = 0.f;
            if (c < cmax) {
                int j = lane + 32*c;
                float e = 0.f;
                if (j <= i) {
                    float delta = fmaxf(1.f - pref[c]*invT, 0.f);
                    float dist = fast_sqrt(delta * (float)(i - j));
                    float eff = fmaxf(__expf(-ag*dist), 1e-5f);
                    e = __expf(raw[c]*eff - M);
                }
                e2[c] = e;
                sm += e;
                u64 ee = pk2(e, e);
                const ulonglong2* vp = (const ulonglong2*)&Vs[j*5];
                ulonglong2 p0 = vp[0], p1 = vp[1], p2 = vp[2], p3 = vp[3];
                fma2(r2[0], ee, p0.x); fma2(r2[1], ee, p0.y);
                fma2(r2[2], ee, p1.x); fma2(r2[3], ee, p1.y);
                fma2(r2[4], ee, p2.x); fma2(r2[5], ee, p2.y);
                fma2(r2[6], ee, p3.x); fma2(r2[7], ee, p3.y);
            }
        }
        sm = warpSum(sm);
        float inv2 = 1.f / sm;

        float* qrow = qs + (((size_t)((b*8 + h)*256 + i)) << 8);
        #pragma unroll
        for (int c = 0; c < 8; c++) qrow[lane + 32*c] = e2[c]*inv2;

        float r[16];
        #pragma unroll
        for (int d = 0; d < 8; d++) upk2(r2[d], r[2*d], r[2*d+1]);
        float o = foldReduce16(r, lane) * inv2;
        if (lane < 16)
            g_O1[((size_t)(b*256 + i))*128 + h*16 + lane] = o;
    }
}

// ---------- block4 attention: scores only (AV moved to avgemm) ----------
__global__ __launch_bounds__(256) void attn4_kernel(const float* __restrict__ gamma,
                                                    float* __restrict__ ks){
    __shared__ float2 rp_s[256];          // {raw, pref}
    __shared__ float red[8], tot[8];
    int g = blockIdx.x;
    int s = g & 1;
    int gh = g >> 1;
    int b = gh >> 7, n = (gh >> 3) & 15, h = gh & 7;
    int tid = threadIdx.x, lane = tid & 31, w = tid >> 5;
    int j = tid;

    const float4* qv = (const float4*)(g_Q4 + n*128 + h*16);
    const float4* kv = (const float4*)(g_K4 + ((size_t)(b*256 + j))*128 + h*16);
    float raw = 0.25f * dot16(qv[0],qv[1],qv[2],qv[3], kv[0],kv[1],kv[2],kv[3]);
    float m = warpMax(raw);
    if (lane == 0) red[w] = m;
    __syncthreads();
    float mx = red[0];
    #pragma unroll
    for (int k2 = 1; k2 < 8; k2++) mx = fmaxf(mx, red[k2]);
    float x = warpInclScan(__expf(raw - mx), lane);
    if (lane == 31) tot[w] = x;
    __syncthreads();
    float off = 0.f;
    #pragma unroll
    for (int k2 = 0; k2 < 8; k2++) if (k2 < w) off += tot[k2];
    rp_s[j] = make_float2(raw, x + off);
    __syncthreads();

    float ag = fabsf(gamma[h]);
    float M = fmaxf(mx, 0.f);     // upper bound for raw*eff over ALL j (eff<=1)

    for (int t = 0; t < 16; t++) {
        int i = w + 16*t + 8*s;   // bijective over 0..255 across (w,t,s)
        float* krow = ks + (((size_t)((b*8 + h)*4096 + i*16 + n)) << 8);
        if (i == 0) {
            #pragma unroll
            for (int c = 0; c < 8; c++) krow[lane + 32*c] = 0.f;
            continue;
        }
        float invT = 1.f / rp_s[i-1].y;
        int cmax = (i + 31) >> 5;

        float e2[8], sm = 0.f, emax = 0.f;
        #pragma unroll
        for (int c = 0; c < 8; c++) {
            e2[c] = 0.f;
            if (c < cmax) {
                int jj = lane + 32*c;
                float e = 0.f;
                if (jj < i) {
                    float2 rpv = rp_s[jj];
                    float delta = fmaxf(1.f - rpv.y*invT, 0.f);
                    float dist = fast_sqrt(delta * (float)(i - jj));
                    float eff = fmaxf(__expf(-ag*dist), 1e-5f);
                    e = __expf(rpv.x*eff - M);
                }
                e2[c] = e;
                sm += e;
                emax = fmaxf(emax, e);
            }
        }
        sm = warpSum(sm);
        emax = warpMax(emax);
        float sos = fminf(1.f/emax, 5.f/sm);   // maxout scale / softmax denom

        #pragma unroll
        for (int c = 0; c < 8; c++) krow[lane + 32*c] = e2[c]*sos;
    }
}

// ---------- avgemm: O4 = ksc @ V4 per (b,h); batched, V-broadcast ----------
// Per (b,h): rows R = i*16+n (4096), cols d (16), K = 256 j.
// Block: 8 warps x 32 rows = 256 rows. Warp-private transposed S staging.
__global__ __launch_bounds__(256) void avgemm_kernel(const float* __restrict__ ks){
    __shared__ __align__(16) float Vs[256*16];     // [j][d], pitch 16
    __shared__ float St[8][16*33];                 // per warp [k][row], pitch 33
    int bt = blockIdx.x;           // 0..511
    int grp = bt >> 4;             // b*8+h
    int tile = bt & 15;            // 256-row tile
    int b = grp >> 3, h = grp & 7;
    int tid = threadIdx.x, lane = tid & 31, w = tid >> 5;

    // load V tile: j = tid, 16 floats
    {
        const float* vsrc = &g_V4[((size_t)(b*256 + tid))*128 + h*16];
        #pragma unroll
        for (int q = 0; q < 4; q++)
            *(float4*)&Vs[tid*16 + q*4] = *(const float4*)&vsrc[q*4];
    }
    __syncthreads();

    const float* Sbase = ks + ((size_t)grp*4096 + tile*256 + w*32)*256;
    u64 acc[8];
    #pragma unroll
    for (int d = 0; d < 8; d++) acc[d] = 0ull;

    for (int k0 = 0; k0 < 256; k0 += 16) {
        // stage 32 rows x 16 k, transposed. lane: rows p*8+(lane>>2), k=4*(lane&3)
        #pragma unroll
        for (int p = 0; p < 4; p++) {
            int rr = p*8 + (lane >> 2);
            int kk = 4*(lane & 3);
            float4 sv = *(const float4*)&Sbase[(size_t)rr*256 + k0 + kk];
            St[w][(kk+0)*33 + rr] = sv.x;
            St[w][(kk+1)*33 + rr] = sv.y;
            St[w][(kk+2)*33 + rr] = sv.z;
            St[w][(kk+3)*33 + rr] = sv.w;
        }
        __syncwarp();
        #pragma unroll
        for (int kk = 0; kk < 16; kk++) {
            float sval = St[w][kk*33 + lane];
            u64 ss = pk2(sval, sval);
            const ulonglong2* vp = (const ulonglong2*)&Vs[(k0 + kk)*16];
            ulonglong2 va = vp[0], vb = vp[1];
            fma2(acc[0], ss, va.x); fma2(acc[1], ss, va.y);
            fma2(acc[2], ss, vb.x); fma2(acc[3], ss, vb.y);
            ulonglong2 vc = vp[2], vd = vp[3];
            fma2(acc[4], ss, vc.x); fma2(acc[5], ss, vc.y);
            fma2(acc[6], ss, vd.x); fma2(acc[7], ss, vd.y);
        }
        __syncwarp();
    }

    int R = tile*256 + w*32 + lane;
    int i = R >> 4, n = R & 15;
    float* orow = &g_O4[((size_t)((b*16 + n)*256 + i))*128 + h*16];
    #pragma unroll
    for (int q = 0; q < 4; q++) {
        float4 o;
        upk2(acc[2*q+0], o.x, o.y);
        upk2(acc[2*q+1], o.z, o.w);
        *(float4*)&orow[q*4] = o;
    }
}

extern "C" void kernel_launch(void* const* d_in, const int* in_sizes, int n_in,
                              void* d_out, int out_size){
    const float* q_emb   = (const float*)d_in[0];
    const float* s_emb   = (const float*)d_in[1];
    const float* b1_Wq   = (const float*)d_in[3];
    const float* b1_bq   = (const float*)d_in[4];
    const float* b1_Wv   = (const float*)d_in[5];
    const float* b1_bv   = (const float*)d_in[6];
    const float* b1_Wo   = (const float*)d_in[7];
    const float* b1_bo   = (const float*)d_in[8];
    const float* b1_gamma= (const float*)d_in[9];
    const float* b1_lng  = (const float*)d_in[10];
    const float* b1_lnb  = (const float*)d_in[11];
    const float* b4_Wq   = (const float*)d_in[12];
    const float* b4_bq   = (const float*)d_in[13];
    const float* b4_Wk   = (const float*)d_in[14];
    const float* b4_bk   = (const float*)d_in[15];
    const float* b4_Wv   = (const float*)d_in[16];
    const float* b4_bv   = (const float*)d_in[17];
    const float* b4_Wo   = (const float*)d_in[18];
    const float* b4_bo   = (const float*)d_in[19];
    const float* b4_gamma= (const float*)d_in[20];
    const float* b4_lng  = (const float*)d_in[21];
    const float* b4_lnb  = (const float*)d_in[22];
    const float* know    = (const float*)d_in[23];

    float* z   = (float*)d_out;              // 4*256*2048
    float* qsc = z + 2097152;                // 4*8*256*256
    float* ksc = z + 4194304;                // 4*8*256*16*256

    proj_kernel<<<97, 256>>>(q_emb, s_emb, know,
                             b1_Wq, b1_bq, b1_Wv, b1_bv,
                             b4_Wk, b4_bk, b4_Wq, b4_bq);
    attn1_kernel<<<dim3(8,8,4), 256>>>(b1_gamma, qsc);
    pv_kernel<<<64, 256>>>(q_emb, b1_Wo, b1_bo, b1_lng, b1_lnb, b4_Wv, b4_bv);
    attn4_kernel<<<1024, 256>>>(b4_gamma, ksc);
    avgemm_kernel<<<512, 256>>>(ksc);
    zgemm_kernel<<<512, 256>>>(b4_Wo, b4_bo, z, know, b4_lng, b4_lnb);
}

// round 12
// speedup vs baseline: 1.0053x; 1.0053x over previous
#include <cuda_runtime.h>
#include <math.h>
#include <float.h>

typedef unsigned long long u64;
#define FULLMASK 0xFFFFFFFFu

// ---------- scratch (no allocations allowed) ----------
__device__ __align__(16) float g_Q1[1024*128];
__device__ __align__(16) float g_V1[1024*128];
__device__ __align__(16) float g_O1[1024*128];
__device__ __align__(16) float g_K4[1024*128];
__device__ __align__(16) float g_V4[1024*128];
__device__ __align__(16) float g_Q4[16*128];
__device__ __align__(16) float g_O4[16384*128];

// ---------- f32x2 packed math ----------
__device__ __forceinline__ u64 pk2(float lo, float hi){
    u64 r; asm("mov.b64 %0, {%1,%2};" : "=l"(r) : "f"(lo), "f"(hi)); return r;
}
__device__ __forceinline__ void upk2(u64 v, float& lo, float& hi){
    asm("mov.b64 {%0,%1}, %2;" : "=f"(lo), "=f"(hi) : "l"(v));
}
__device__ __forceinline__ void fma2(u64& d, u64 a, u64 b){
    asm("fma.rn.f32x2 %0, %1, %2, %0;" : "+l"(d) : "l"(a), "l"(b));
}

// ---------- helpers ----------
__device__ __forceinline__ float warpMax(float v){
    #pragma unroll
    for (int o = 16; o; o >>= 1) v = fmaxf(v, __shfl_xor_sync(FULLMASK, v, o));
    return v;
}
__device__ __forceinline__ float warpSum(float v){
    #pragma unroll
    for (int o = 16; o; o >>= 1) v += __shfl_xor_sync(FULLMASK, v, o);
    return v;
}
__device__ __forceinline__ float warpInclScan(float x, int lane){
    #pragma unroll
    for (int o = 1; o < 32; o <<= 1) {
        float y = __shfl_up_sync(FULLMASK, x, o);
        if (lane >= o) x += y;
    }
    return x;
}
__device__ __forceinline__ float fast_sqrt(float x){
    float r; asm("sqrt.approx.f32 %0, %1;" : "=f"(r) : "f"(x)); return r;
}
__device__ __forceinline__ float dot16(const float4 a0, const float4 a1, const float4 a2, const float4 a3,
                                       const float4 b0, const float4 b1, const float4 b2, const float4 b3){
    float s;
    s  = a0.x*b0.x + a0.y*b0.y + a0.z*b0.z + a0.w*b0.w;
    s += a1.x*b1.x + a1.y*b1.y + a1.z*b1.z + a1.w*b1.w;
    s += a2.x*b2.x + a2.y*b2.y + a2.z*b2.z + a2.w*b2.w;
    s += a3.x*b3.x + a3.y*b3.y + a3.z*b3.z + a3.w*b3.w;
    return s;
}
// Reduce 16 accumulators across 32 lanes; lane l gets sum over lanes of r[l&15].
__device__ __forceinline__ float foldReduce16(float r[16], int lane){
    #pragma unroll
    for (int d = 0; d < 16; d++) r[d] += __shfl_xor_sync(FULLMASK, r[d], 16);
    #pragma unroll
    for (int d = 0; d < 8; d++) {
        float x = (lane & 8) ? r[d] : r[d+8];
        float y = __shfl_xor_sync(FULLMASK, x, 8);
        r[d] = ((lane & 8) ? r[d+8] : r[d]) + y;
    }
    #pragma unroll
    for (int d = 0; d < 4; d++) {
        float x = (lane & 4) ? r[d] : r[d+4];
        float y = __shfl_xor_sync(FULLMASK, x, 4);
        r[d] = ((lane & 4) ? r[d+4] : r[d]) + y;
    }
    #pragma unroll
    for (int d = 0; d < 2; d++) {
        float x = (lane & 2) ? r[d] : r[d+2];
        float y = __shfl_xor_sync(FULLMASK, x, 2);
        r[d] = ((lane & 2) ? r[d+2] : r[d]) + y;
    }
    float x = (lane & 1) ? r[0] : r[1];
    float y = __shfl_xor_sync(FULLMASK, x, 1);
    return ((lane & 1) ? r[1] : r[0]) + y;
}

// ---------- GEMM core: out[row0..row0+31][0..127] = X@W^T + bias (f32x2) ----------
__device__ __forceinline__ void gemm_core(const float* __restrict__ X, const float* __restrict__ W,
                                          const float* __restrict__ bias, float* __restrict__ out,
                                          int M, int row0, float* Wt, float* Xs){
    int tid = threadIdx.x, tx = tid & 31, ty = tid >> 5;
    u64 acc[4][2];
    #pragma unroll
    for (int q = 0; q < 4; q++){ acc[q][0] = 0ull; acc[q][1] = 0ull; }

    for (int k0 = 0; k0 < 128; k0 += 32) {
        #pragma unroll
        for (int iL = 0; iL < 16; iL++) {
            int idx = tid + 256*iL;
            int c = idx >> 5, kk = idx & 31;
            Wt[kk*132 + c] = W[c*128 + k0 + kk];
        }
        #pragma unroll
        for (int iL = 0; iL < 4; iL++) {
            int idx = tid + 256*iL;
            int r = idx >> 5, kk = idx & 31;
            int grow = row0 + r;
            Xs[r*33 + kk] = (grow < M) ? X[(size_t)grow*128 + k0 + kk] : 0.f;
        }
        __syncthreads();
        #pragma unroll
        for (int kk = 0; kk < 32; kk++) {
            ulonglong2 wv = *(const ulonglong2*)&Wt[kk*132 + tx*4];
            #pragma unroll
            for (int q = 0; q < 4; q++) {
                float xv = Xs[(ty + 8*q)*33 + kk];
                u64 xx = pk2(xv, xv);
                fma2(acc[q][0], xx, wv.x);
                fma2(acc[q][1], xx, wv.y);
            }
        }
        __syncthreads();
    }
    float4 bv = *(const float4*)&bias[tx*4];
    #pragma unroll
    for (int q = 0; q < 4; q++) {
        int grow = row0 + ty + 8*q;
        if (grow < M) {
            float4 o;
            upk2(acc[q][0], o.x, o.y);
            upk2(acc[q][1], o.z, o.w);
            o.x += bv.x; o.y += bv.y; o.z += bv.z; o.w += bv.w;
            *(float4*)&out[(size_t)grow*128 + tx*4] = o;
        }
    }
}

// ---------- fused projections: Q1 | V1 | K4 | Q4 in one launch ----------
__global__ __launch_bounds__(256) void proj_kernel(const float* __restrict__ q_emb,
                                                   const float* __restrict__ s_emb,
                                                   const float* __restrict__ know,
                                                   const float* __restrict__ Wq1, const float* __restrict__ bq1,
                                                   const float* __restrict__ Wv1, const float* __restrict__ bv1,
                                                   const float* __restrict__ Wk4, const float* __restrict__ bk4,
                                                   const float* __restrict__ Wq4, const float* __restrict__ bq4){
    __shared__ __align__(16) float Wt[32*132];
    __shared__ float Xs[32*33];
    int bx = blockIdx.x;
    const float *X, *W, *bias; float* out; int M, row0;
    if (bx < 32)      { X=q_emb; W=Wq1; bias=bq1; out=g_Q1; M=1024; row0=bx*32; }
    else if (bx < 64) { X=s_emb; W=Wv1; bias=bv1; out=g_V1; M=1024; row0=(bx-32)*32; }
    else if (bx < 96) { X=q_emb; W=Wk4; bias=bk4; out=g_K4; M=1024; row0=(bx-64)*32; }
    else              { X=know;  W=Wq4; bias=bq4; out=g_Q4; M=16;   row0=0; }
    gemm_core(X, W, bias, out, M, row0, Wt, Xs);
}

// ---------- fused P+V4 (16-row tiles): V4 = LN(O1@Wo + b + q_emb) @ Wv^T + bv ----------
__global__ __launch_bounds__(256) void pv_kernel(const float* __restrict__ q_emb,
                                                 const float* __restrict__ Wo, const float* __restrict__ bo,
                                                 const float* __restrict__ lng, const float* __restrict__ lnb,
                                                 const float* __restrict__ Wv, const float* __restrict__ bv4){
    __shared__ __align__(16) float Wt[32*132];
    __shared__ float Xs[16*33];
    __shared__ __align__(16) float Os[16*132];
    int row0 = blockIdx.x * 16;
    int tid = threadIdx.x, tx = tid & 31, ty = tid >> 5;

    u64 acc[2][2];
    #pragma unroll
    for (int q = 0; q < 2; q++){ acc[q][0] = 0ull; acc[q][1] = 0ull; }
    for (int k0 = 0; k0 < 128; k0 += 32) {
        #pragma unroll
        for (int iL = 0; iL < 16; iL++) {
            int idx = tid + 256*iL;
            int c = idx >> 5, kk = idx & 31;
            Wt[kk*132 + c] = Wo[c*128 + k0 + kk];
        }
        #pragma unroll
        for (int iL = 0; iL < 2; iL++) {
            int idx = tid + 256*iL;
            int r = idx >> 5, kk = idx & 31;
            Xs[r*33 + kk] = g_O1[(size_t)(row0 + r)*128 + k0 + kk];
        }
        __syncthreads();
        #pragma unroll
        for (int kk = 0; kk < 32; kk++) {
            ulonglong2 wv = *(const ulonglong2*)&Wt[kk*132 + tx*4];
            #pragma unroll
            for (int q = 0; q < 2; q++) {
                float xv = Xs[(ty + 8*q)*33 + kk];
                u64 xx = pk2(xv, xv);
                fma2(acc[q][0], xx, wv.x);
                fma2(acc[q][1], xx, wv.y);
            }
        }
        __syncthreads();
    }
    {
        float4 bv = *(const float4*)&bo[tx*4];
        #pragma unroll
        for (int q = 0; q < 2; q++) {
            int r = ty + 8*q;
            float4 rv = *(const float4*)&q_emb[(size_t)(row0 + r)*128 + tx*4];
            float4 o;
            upk2(acc[q][0], o.x, o.y);
            upk2(acc[q][1], o.z, o.w);
            o.x += bv.x + rv.x; o.y += bv.y + rv.y;
            o.z += bv.z + rv.z; o.w += bv.w + rv.w;
            *(float4*)&Os[r*132 + tx*4] = o;
        }
    }
    __syncthreads();
    #pragma unroll
    for (int q = 0; q < 2; q++) {
        int r = ty + 8*q;
        float v[4];
        #pragma unroll
        for (int c4 = 0; c4 < 4; c4++) v[c4] = Os[r*132 + tx + 32*c4];
        float s = v[0] + v[1] + v[2] + v[3];
        s = warpSum(s);
        float mean = s * 0.0078125f;
        float vs = 0.f;
        #pragma unroll
        for (int c4 = 0; c4 < 4; c4++) { float d = v[c4] - mean; vs += d*d; }
        vs = warpSum(vs);
        float rs = rsqrtf(vs * 0.0078125f + 1e-5f);
        #pragma unroll
        for (int c4 = 0; c4 < 4; c4++) {
            int c = tx + 32*c4;
            Os[r*132 + c] = (v[c4] - mean)*rs*lng[c] + lnb[c];
        }
    }
    __syncthreads();

    #pragma unroll
    for (int q = 0; q < 2; q++){ acc[q][0] = 0ull; acc[q][1] = 0ull; }
    for (int k0 = 0; k0 < 128; k0 += 32) {
        #pragma unroll
        for (int iL = 0; iL < 16; iL++) {
            int idx = tid + 256*iL;
            int c = idx >> 5, kk = idx & 31;
            Wt[kk*132 + c] = Wv[c*128 + k0 + kk];
        }
        __syncthreads();
        #pragma unroll
        for (int kk = 0; kk < 32; kk++) {
            ulonglong2 wv = *(const ulonglong2*)&Wt[kk*132 + tx*4];
            #pragma unroll
            for (int q = 0; q < 2; q++) {
                float xv = Os[(ty + 8*q)*132 + k0 + kk];
                u64 xx = pk2(xv, xv);
                fma2(acc[q][0], xx, wv.x);
                fma2(acc[q][1], xx, wv.y);
            }
        }
        __syncthreads();
    }
    {
        float4 bv = *(const float4*)&bv4[tx*4];
        #pragma unroll
        for (int q = 0; q < 2; q++) {
            int grow = row0 + ty + 8*q;
            float4 o;
            upk2(acc[q][0], o.x, o.y);
            upk2(acc[q][1], o.z, o.w);
            o.x += bv.x; o.y += bv.y; o.z += bv.z; o.w += bv.w;
            *(float4*)&g_V4[(size_t)grow*128 + tx*4] = o;
        }
    }
}

// ---------- final z GEMM + LN + scatter ----------
__global__ __launch_bounds__(256) void zgemm_kernel(const float* __restrict__ W,
                                                    const float* __restrict__ bias,
                                                    float* __restrict__ out,
                                                    const float* __restrict__ know,
                                                    const float* __restrict__ lng,
                                                    const float* __restrict__ lnb){
    __shared__ __align__(16) float Wt[32*132];
    __shared__ float Xs[32*33];
    __shared__ __align__(16) float Os[32*132];
    int row0 = blockIdx.x * 32;
    int tid = threadIdx.x, tx = tid & 31, ty = tid >> 5;

    u64 acc[4][2];
    #pragma unroll
    for (int q = 0; q < 4; q++){ acc[q][0] = 0ull; acc[q][1] = 0ull; }
    for (int k0 = 0; k0 < 128; k0 += 32) {
        #pragma unroll
        for (int iL = 0; iL < 16; iL++) {
            int idx = tid + 256*iL;
            int c = idx >> 5, kk = idx & 31;
            Wt[kk*132 + c] = W[c*128 + k0 + kk];
        }
        #pragma unroll
        for (int iL = 0; iL < 4; iL++) {
            int idx = tid + 256*iL;
            int r = idx >> 5, kk = idx & 31;
            Xs[r*33 + kk] = g_O4[(size_t)(row0 + r)*128 + k0 + kk];
        }
        __syncthreads();
        #pragma unroll
        for (int kk = 0; kk < 32; kk++) {
            ulonglong2 wv = *(const ulonglong2*)&Wt[kk*132 + tx*4];
            #pragma unroll
            for (int q = 0; q < 4; q++) {
                float xv = Xs[(ty + 8*q)*33 + kk];
                u64 xx = pk2(xv, xv);
                fma2(acc[q][0], xx, wv.x);
                fma2(acc[q][1], xx, wv.y);
            }
        }
        __syncthreads();
    }
    {
        float4 bv = *(const float4*)&bias[tx*4];
        #pragma unroll
        for (int q = 0; q < 4; q++) {
            int r = ty + 8*q;
            int grow = row0 + r;
            int nn = (grow >> 8) & 15;
            float4 rv = *(const float4*)&know[nn*128 + tx*4];
            float4 o;
            upk2(acc[q][0], o.x, o.y);
            upk2(acc[q][1], o.z, o.w);
            o.x += bv.x + rv.x; o.y += bv.y + rv.y;
            o.z += bv.z + rv.z; o.w += bv.w + rv.w;
            *(float4*)&Os[r*132 + tx*4] = o;
        }
    }
    __syncthreads();
    #pragma unroll
    for (int q = 0; q < 4; q++) {
        int r = ty + 8*q;
        int grow = row0 + r;
        float v[4];
        #pragma unroll
        for (int c4 = 0; c4 < 4; c4++) v[c4] = Os[r*132 + tx + 32*c4];
        float s = v[0] + v[1] + v[2] + v[3];
        s = warpSum(s);
        float mean = s * 0.0078125f;
        float vs = 0.f;
        #pragma unroll
        for (int c4 = 0; c4 < 4; c4++) { float d = v[c4] - mean; vs += d*d; }
        vs = warpSum(vs);
        float rs = rsqrtf(vs * 0.0078125f + 1e-5f);
        int bb = grow >> 12, nn = (grow >> 8) & 15, ii = grow & 255;
        size_t ob = ((size_t)(bb*256 + ii))*2048 + (size_t)nn*128;
        #pragma unroll
        for (int c4 = 0; c4 < 4; c4++) {
            int c = tx + 32*c4;
            out[ob + c] = (v[c4] - mean)*rs*lng[c] + lnb[c];
        }
    }
}

// ---------- block1 attention (causal incl diag, kq_same, no maxout) ----------
__global__ __launch_bounds__(256) void attn1_kernel(const float* __restrict__ gamma,
                                                    float* __restrict__ qs){
    __shared__ float4 Ks[256*5];   // 80B pitch -> conflict-free float4
    __shared__ float4 Vs[256*5];
    int split = blockIdx.x, h = blockIdx.y, b = blockIdx.z;
    int tid = threadIdx.x, lane = tid & 31, w = tid >> 5;

    const float4* qg = (const float4*)(g_Q1 + (size_t)b*32768) + h*4;
    const float4* vg = (const float4*)(g_V1 + (size_t)b*32768) + h*4;
    #pragma unroll
    for (int d4 = 0; d4 < 4; d4++) {
        Ks[tid*5 + d4] = qg[(size_t)tid*32 + d4];
        Vs[tid*5 + d4] = vg[(size_t)tid*32 + d4];
    }
    __syncthreads();
    float ag = fabsf(gamma[h]);

    for (int t = 0; t < 4; t++) {
        int i = split + 8*w + 64*t;       // bijective over 0..255
        int cmax = (i >> 5) + 1;
        float4 q0 = Ks[i*5+0], q1 = Ks[i*5+1], q2 = Ks[i*5+2], q3 = Ks[i*5+3];

        float raw[8], mxv = -FLT_MAX;
        #pragma unroll
        for (int c = 0; c < 8; c++) {
            raw[c] = -FLT_MAX;
            if (c < cmax) {
                int j = lane + 32*c;
                if (j <= i)
                    raw[c] = 0.25f * dot16(q0,q1,q2,q3, Ks[j*5+0],Ks[j*5+1],Ks[j*5+2],Ks[j*5+3]);
                mxv = fmaxf(mxv, raw[c]);
            }
        }
        mxv = warpMax(mxv);

        float pref[8]; float base = 0.f;
        #pragma unroll
        for (int c = 0; c < 8; c++) {
            pref[c] = 0.f;
            if (c < cmax) {
                int j = lane + 32*c;
                float ev = (j <= i) ? __expf(raw[c] - mxv) : 0.f;
                float x = warpInclScan(ev, lane);
                pref[c] = base + x;
                base += __shfl_sync(FULLMASK, x, 31);
            }
        }
        float invT = 1.f / base;

        float M = fmaxf(mxv, 0.f);
        float e2[8], sm = 0.f;
        u64 r2[8];
        #pragma unroll
        for (int d = 0; d < 8; d++) r2[d] = 0ull;
        #pragma unroll
        for (int c = 0; c < 8; c++) {
            e2[c] = 0.f;
            if (c < cmax) {
                int j = lane + 32*c;
                float e = 0.f;
                if (j <= i) {
                    float delta = fmaxf(1.f - pref[c]*invT, 0.f);
                    float dist = fast_sqrt(delta * (float)(i - j));
                    float eff = fmaxf(__expf(-ag*dist), 1e-5f);
                    e = __expf(raw[c]*eff - M);
                }
                e2[c] = e;
                sm += e;
                u64 ee = pk2(e, e);
                const ulonglong2* vp = (const ulonglong2*)&Vs[j*5];
                ulonglong2 p0 = vp[0], p1 = vp[1], p2 = vp[2], p3 = vp[3];
                fma2(r2[0], ee, p0.x); fma2(r2[1], ee, p0.y);
                fma2(r2[2], ee, p1.x); fma2(r2[3], ee, p1.y);
                fma2(r2[4], ee, p2.x); fma2(r2[5], ee, p2.y);
                fma2(r2[6], ee, p3.x); fma2(r2[7], ee, p3.y);
            }
        }
        sm = warpSum(sm);
        float inv2 = 1.f / sm;

        float* qrow = qs + (((size_t)((b*8 + h)*256 + i)) << 8);
        #pragma unroll
        for (int c = 0; c < 8; c++) qrow[lane + 32*c] = e2[c]*inv2;

        float r[16];
        #pragma unroll
        for (int d = 0; d < 8; d++) upk2(r2[d], r[2*d], r[2*d+1]);
        float o = foldReduce16(r, lane) * inv2;
        if (lane < 16)
            g_O1[((size_t)(b*256 + i))*128 + h*16 + lane] = o;
    }
}

// ---------- block4 attention: scores only (AV in avgemm) ----------
__global__ __launch_bounds__(256) void attn4_kernel(const float* __restrict__ gamma,
                                                    float* __restrict__ ks){
    __shared__ float2 rp_s[256];          // {raw, pref}
    __shared__ float red[8], tot[8];
    int g = blockIdx.x;
    int s = g & 1;
    int gh = g >> 1;
    int b = gh >> 7, n = (gh >> 3) & 15, h = gh & 7;
    int tid = threadIdx.x, lane = tid & 31, w = tid >> 5;
    int j = tid;

    const float4* qv = (const float4*)(g_Q4 + n*128 + h*16);
    const float4* kv = (const float4*)(g_K4 + ((size_t)(b*256 + j))*128 + h*16);
    float raw = 0.25f * dot16(qv[0],qv[1],qv[2],qv[3], kv[0],kv[1],kv[2],kv[3]);
    float m = warpMax(raw);
    if (lane == 0) red[w] = m;
    __syncthreads();
    float mx = red[0];
    #pragma unroll
    for (int k2 = 1; k2 < 8; k2++) mx = fmaxf(mx, red[k2]);
    float x = warpInclScan(__expf(raw - mx), lane);
    if (lane == 31) tot[w] = x;
    __syncthreads();
    float off = 0.f;
    #pragma unroll
    for (int k2 = 0; k2 < 8; k2++) if (k2 < w) off += tot[k2];
    rp_s[j] = make_float2(raw, x + off);
    __syncthreads();

    float ag = fabsf(gamma[h]);
    float M = fmaxf(mx, 0.f);     // upper bound for raw*eff over ALL j (eff<=1)

    for (int t = 0; t < 16; t++) {
        int i = w + 16*t + 8*s;   // bijective over 0..255 across (w,t,s)
        float* krow = ks + (((size_t)((b*8 + h)*4096 + i*16 + n)) << 8);
        if (i == 0) {
            #pragma unroll
            for (int c = 0; c < 8; c++) krow[lane + 32*c] = 0.f;
            continue;
        }
        float invT = 1.f / rp_s[i-1].y;
        int cmax = (i + 31) >> 5;

        float e2[8], sm = 0.f, emax = 0.f;
        #pragma unroll
        for (int c = 0; c < 8; c++) {
            e2[c] = 0.f;
            if (c < cmax) {
                int jj = lane + 32*c;
                float e = 0.f;
                if (jj < i) {
                    float2 rpv = rp_s[jj];
                    float delta = fmaxf(1.f - rpv.y*invT, 0.f);
                    float dist = fast_sqrt(delta * (float)(i - jj));
                    float eff = fmaxf(__expf(-ag*dist), 1e-5f);
                    e = __expf(rpv.x*eff - M);
                }
                e2[c] = e;
                sm += e;
                emax = fmaxf(emax, e);
            }
        }
        sm = warpSum(sm);
        emax = warpMax(emax);
        float sos = fminf(1.f/emax, 5.f/sm);   // maxout scale / softmax denom

        #pragma unroll
        for (int c = 0; c < 8; c++) krow[lane + 32*c] = e2[c]*sos;
    }
}

// ---------- avgemm v2: O4 = ksc @ V4; block = 256 rows x 16 d, K = 256 ----------
// Per (b,h): 4096 rows (R = i*16+n), 16 d. grid = 32 groups x 16 row-tiles.
// S staged transposed block-wide: S_T[k][r], pitch 260 -> conflict-free inner LDS.
__global__ __launch_bounds__(256) void avgemm_kernel(const float* __restrict__ ks){
    __shared__ float S_T[16*260];                  // 16.6 KB
    __shared__ __align__(16) float Vs[256*16];     // 16 KB, [j][d]
    int bt = blockIdx.x;           // 0..511
    int grp = bt >> 4;             // b*8+h
    int tile = bt & 15;            // 256-row tile
    int b = grp >> 3, h = grp & 7;
    int tid = threadIdx.x;
    int rg = tid >> 2;             // 0..63
    int dpg = tid & 3;             // 0..3 -> d = dpg*4..dpg*4+3

    // load V tile: j = tid, 16 floats
    {
        const float* vsrc = &g_V4[((size_t)(b*256 + tid))*128 + h*16];
        #pragma unroll
        for (int q = 0; q < 4; q++)
            *(float4*)&Vs[tid*16 + q*4] = *(const float4*)&vsrc[q*4];
    }

    const float* Sbase = ks + ((size_t)grp*4096 + tile*256)*256;
    u64 acc[4][2];
    #pragma unroll
    for (int q = 0; q < 4; q++){ acc[q][0] = 0ull; acc[q][1] = 0ull; }

    for (int k0 = 0; k0 < 256; k0 += 16) {
        // stage: thread loads 4 float4 (rows rg + 64p, k-chunk dpg*4), stores transposed
        __syncthreads();
        #pragma unroll
        for (int p = 0; p < 4; p++) {
            int r = rg + 64*p;
            float4 sv = *(const float4*)&Sbase[(size_t)r*256 + k0 + dpg*4];
            S_T[(dpg*4+0)*260 + r] = sv.x;
            S_T[(dpg*4+1)*260 + r] = sv.y;
            S_T[(dpg*4+2)*260 + r] = sv.z;
            S_T[(dpg*4+3)*260 + r] = sv.w;
        }
        __syncthreads();
        #pragma unroll
        for (int kk = 0; kk < 16; kk++) {
            ulonglong2 vv = *(const ulonglong2*)&Vs[(k0 + kk)*16 + dpg*4];
            #pragma unroll
            for (int q = 0; q < 4; q++) {
                float sval = S_T[kk*260 + rg + 64*q];
                u64 ss = pk2(sval, sval);
                fma2(acc[q][0], ss, vv.x);
                fma2(acc[q][1], ss, vv.y);
            }
        }
    }

    #pragma unroll
    for (int q = 0; q < 4; q++) {
        int R = tile*256 + rg + 64*q;
        int i = R >> 4, n = R & 15;
        float* orow = &g_O4[((size_t)((b*16 + n)*256 + i))*128 + h*16 + dpg*4];
        float4 o;
        upk2(acc[q][0], o.x, o.y);
        upk2(acc[q][1], o.z, o.w);
        *(float4*)orow = o;
    }
}

extern "C" void kernel_launch(void* const* d_in, const int* in_sizes, int n_in,
                              void* d_out, int out_size){
    const float* q_emb   = (const float*)d_in[0];
    const float* s_emb   = (const float*)d_in[1];
    const float* b1_Wq   = (const float*)d_in[3];
    const float* b1_bq   = (const float*)d_in[4];
    const float* b1_Wv   = (const float*)d_in[5];
    const float* b1_bv   = (const float*)d_in[6];
    const float* b1_Wo   = (const float*)d_in[7];
    const float* b1_bo   = (const float*)d_in[8];
    const float* b1_gamma= (const float*)d_in[9];
    const float* b1_lng  = (const float*)d_in[10];
    const float* b1_lnb  = (const float*)d_in[11];
    const float* b4_Wq   = (const float*)d_in[12];
    const float* b4_bq   = (const float*)d_in[13];
    const float* b4_Wk   = (const float*)d_in[14];
    const float* b4_bk   = (const float*)d_in[15];
    const float* b4_Wv   = (const float*)d_in[16];
    const float* b4_bv   = (const float*)d_in[17];
    const float* b4_Wo   = (const float*)d_in[18];
    const float* b4_bo   = (const float*)d_in[19];
    const float* b4_gamma= (const float*)d_in[20];
    const float* b4_lng  = (const float*)d_in[21];
    const float* b4_lnb  = (const float*)d_in[22];
    const float* know    = (const float*)d_in[23];

    float* z   = (float*)d_out;              // 4*256*2048
    float* qsc = z + 2097152;                // 4*8*256*256
    float* ksc = z + 4194304;                // 4*8*256*16*256

    proj_kernel<<<97, 256>>>(q_emb, s_emb, know,
                             b1_Wq, b1_bq, b1_Wv, b1_bv,
                             b4_Wk, b4_bk, b4_Wq, b4_bq);
    attn1_kernel<<<dim3(8,8,4), 256>>>(b1_gamma, qsc);
    pv_kernel<<<64, 256>>>(q_emb, b1_Wo, b1_bo, b1_lng, b1_lnb, b4_Wv, b4_bv);
    attn4_kernel<<<1024, 256>>>(b4_gamma, ksc);
    avgemm_kernel<<<512, 256>>>(ksc);
    zgemm_kernel<<<512, 256>>>(b4_Wo, b4_bo, z, know, b4_lng, b4_lnb);
}

// round 13
// speedup vs baseline: 1.2199x; 1.2134x over previous
#include <cuda_runtime.h>
#include <math.h>
#include <float.h>

typedef unsigned long long u64;
#define FULLMASK 0xFFFFFFFFu

// ---------- scratch (no allocations allowed) ----------
__device__ __align__(16) float g_Q1[1024*128];
__device__ __align__(16) float g_V1[1024*128];
__device__ __align__(16) float g_O1[1024*128];
__device__ __align__(16) float g_K4[1024*128];
__device__ __align__(16) float g_V4[1024*128];
__device__ __align__(16) float g_Q4[16*128];
__device__ __align__(16) float g_O4[16384*128];

// ---------- f32x2 packed math ----------
__device__ __forceinline__ u64 pk2(float lo, float hi){
    u64 r; asm("mov.b64 %0, {%1,%2};" : "=l"(r) : "f"(lo), "f"(hi)); return r;
}
__device__ __forceinline__ void upk2(u64 v, float& lo, float& hi){
    asm("mov.b64 {%0,%1}, %2;" : "=f"(lo), "=f"(hi) : "l"(v));
}
__device__ __forceinline__ void fma2(u64& d, u64 a, u64 b){
    asm("fma.rn.f32x2 %0, %1, %2, %0;" : "+l"(d) : "l"(a), "l"(b));
}

// ---------- helpers ----------
__device__ __forceinline__ float warpMax(float v){
    #pragma unroll
    for (int o = 16; o; o >>= 1) v = fmaxf(v, __shfl_xor_sync(FULLMASK, v, o));
    return v;
}
__device__ __forceinline__ float warpSum(float v){
    #pragma unroll
    for (int o = 16; o; o >>= 1) v += __shfl_xor_sync(FULLMASK, v, o);
    return v;
}
__device__ __forceinline__ float warpInclScan(float x, int lane){
    #pragma unroll
    for (int o = 1; o < 32; o <<= 1) {
        float y = __shfl_up_sync(FULLMASK, x, o);
        if (lane >= o) x += y;
    }
    return x;
}
__device__ __forceinline__ float fast_sqrt(float x){
    float r; asm("sqrt.approx.f32 %0, %1;" : "=f"(r) : "f"(x)); return r;
}
__device__ __forceinline__ float dot16(const float4 a0, const float4 a1, const float4 a2, const float4 a3,
                                       const float4 b0, const float4 b1, const float4 b2, const float4 b3){
    float s;
    s  = a0.x*b0.x + a0.y*b0.y + a0.z*b0.z + a0.w*b0.w;
    s += a1.x*b1.x + a1.y*b1.y + a1.z*b1.z + a1.w*b1.w;
    s += a2.x*b2.x + a2.y*b2.y + a2.z*b2.z + a2.w*b2.w;
    s += a3.x*b3.x + a3.y*b3.y + a3.z*b3.z + a3.w*b3.w;
    return s;
}
// Reduce 16 accumulators across 32 lanes; lane l gets sum over lanes of r[l&15].
__device__ __forceinline__ float foldReduce16(float r[16], int lane){
    #pragma unroll
    for (int d = 0; d < 16; d++) r[d] += __shfl_xor_sync(FULLMASK, r[d], 16);
    #pragma unroll
    for (int d = 0; d < 8; d++) {
        float x = (lane & 8) ? r[d] : r[d+8];
        float y = __shfl_xor_sync(FULLMASK, x, 8);
        r[d] = ((lane & 8) ? r[d+8] : r[d]) + y;
    }
    #pragma unroll
    for (int d = 0; d < 4; d++) {
        float x = (lane & 4) ? r[d] : r[d+4];
        float y = __shfl_xor_sync(FULLMASK, x, 4);
        r[d] = ((lane & 4) ? r[d+4] : r[d]) + y;
    }
    #pragma unroll
    for (int d = 0; d < 2; d++) {
        float x = (lane & 2) ? r[d] : r[d+2];
        float y = __shfl_xor_sync(FULLMASK, x, 2);
        r[d] = ((lane & 2) ? r[d+2] : r[d]) + y;
    }
    float x = (lane & 1) ? r[0] : r[1];
    float y = __shfl_xor_sync(FULLMASK, x, 1);
    return ((lane & 1) ? r[1] : r[0]) + y;
}

// ---------- GEMM core 16-row tile: out[row0..row0+15] = X@W^T + bias ----------
__device__ __forceinline__ void gemm_core16(const float* __restrict__ X, const float* __restrict__ W,
                                            const float* __restrict__ bias, float* __restrict__ out,
                                            int M, int row0, float* Wt, float* Xs){
    int tid = threadIdx.x, tx = tid & 31, ty = tid >> 5;
    u64 acc[2][2];
    #pragma unroll
    for (int q = 0; q < 2; q++){ acc[q][0] = 0ull; acc[q][1] = 0ull; }

    for (int k0 = 0; k0 < 128; k0 += 32) {
        #pragma unroll
        for (int iL = 0; iL < 16; iL++) {
            int idx = tid + 256*iL;
            int c = idx >> 5, kk = idx & 31;
            Wt[kk*132 + c] = W[c*128 + k0 + kk];
        }
        #pragma unroll
        for (int iL = 0; iL < 2; iL++) {
            int idx = tid + 256*iL;
            int r = idx >> 5, kk = idx & 31;
            int grow = row0 + r;
            Xs[r*33 + kk] = (grow < M) ? X[(size_t)grow*128 + k0 + kk] : 0.f;
        }
        __syncthreads();
        #pragma unroll
        for (int kk = 0; kk < 32; kk++) {
            ulonglong2 wv = *(const ulonglong2*)&Wt[kk*132 + tx*4];
            #pragma unroll
            for (int q = 0; q < 2; q++) {
                float xv = Xs[(ty + 8*q)*33 + kk];
                u64 xx = pk2(xv, xv);
                fma2(acc[q][0], xx, wv.x);
                fma2(acc[q][1], xx, wv.y);
            }
        }
        __syncthreads();
    }
    float4 bv = *(const float4*)&bias[tx*4];
    #pragma unroll
    for (int q = 0; q < 2; q++) {
        int grow = row0 + ty + 8*q;
        if (grow < M) {
            float4 o;
            upk2(acc[q][0], o.x, o.y);
            upk2(acc[q][1], o.z, o.w);
            o.x += bv.x; o.y += bv.y; o.z += bv.z; o.w += bv.w;
            *(float4*)&out[(size_t)grow*128 + tx*4] = o;
        }
    }
}

// ---------- fused projections: Q1 | V1 | K4 | Q4, 16-row tiles (193 blocks) ----------
__global__ __launch_bounds__(256) void proj_kernel(const float* __restrict__ q_emb,
                                                   const float* __restrict__ s_emb,
                                                   const float* __restrict__ know,
                                                   const float* __restrict__ Wq1, const float* __restrict__ bq1,
                                                   const float* __restrict__ Wv1, const float* __restrict__ bv1,
                                                   const float* __restrict__ Wk4, const float* __restrict__ bk4,
                                                   const float* __restrict__ Wq4, const float* __restrict__ bq4){
    __shared__ __align__(16) float Wt[32*132];
    __shared__ float Xs[16*33];
    int bx = blockIdx.x;
    const float *X, *W, *bias; float* out; int M, row0;
    if (bx < 64)       { X=q_emb; W=Wq1; bias=bq1; out=g_Q1; M=1024; row0=bx*16; }
    else if (bx < 128) { X=s_emb; W=Wv1; bias=bv1; out=g_V1; M=1024; row0=(bx-64)*16; }
    else if (bx < 192) { X=q_emb; W=Wk4; bias=bk4; out=g_K4; M=1024; row0=(bx-128)*16; }
    else               { X=know;  W=Wq4; bias=bq4; out=g_Q4; M=16;   row0=0; }
    gemm_core16(X, W, bias, out, M, row0, Wt, Xs);
}

// ---------- fused P+V4 (16-row tiles): V4 = LN(O1@Wo + b + q_emb) @ Wv^T + bv ----------
__global__ __launch_bounds__(256) void pv_kernel(const float* __restrict__ q_emb,
                                                 const float* __restrict__ Wo, const float* __restrict__ bo,
                                                 const float* __restrict__ lng, const float* __restrict__ lnb,
                                                 const float* __restrict__ Wv, const float* __restrict__ bv4){
    __shared__ __align__(16) float Wt[32*132];
    __shared__ float Xs[16*33];
    __shared__ __align__(16) float Os[16*132];
    int row0 = blockIdx.x * 16;
    int tid = threadIdx.x, tx = tid & 31, ty = tid >> 5;

    u64 acc[2][2];
    #pragma unroll
    for (int q = 0; q < 2; q++){ acc[q][0] = 0ull; acc[q][1] = 0ull; }
    for (int k0 = 0; k0 < 128; k0 += 32) {
        #pragma unroll
        for (int iL = 0; iL < 16; iL++) {
            int idx = tid + 256*iL;
            int c = idx >> 5, kk = idx & 31;
            Wt[kk*132 + c] = Wo[c*128 + k0 + kk];
        }
        #pragma unroll
        for (int iL = 0; iL < 2; iL++) {
            int idx = tid + 256*iL;
            int r = idx >> 5, kk = idx & 31;
            Xs[r*33 + kk] = g_O1[(size_t)(row0 + r)*128 + k0 + kk];
        }
        __syncthreads();
        #pragma unroll
        for (int kk = 0; kk < 32; kk++) {
            ulonglong2 wv = *(const ulonglong2*)&Wt[kk*132 + tx*4];
            #pragma unroll
            for (int q = 0; q < 2; q++) {
                float xv = Xs[(ty + 8*q)*33 + kk];
                u64 xx = pk2(xv, xv);
                fma2(acc[q][0], xx, wv.x);
                fma2(acc[q][1], xx, wv.y);
            }
        }
        __syncthreads();
    }
    {
        float4 bv = *(const float4*)&bo[tx*4];
        #pragma unroll
        for (int q = 0; q < 2; q++) {
            int r = ty + 8*q;
            float4 rv = *(const float4*)&q_emb[(size_t)(row0 + r)*128 + tx*4];
            float4 o;
            upk2(acc[q][0], o.x, o.y);
            upk2(acc[q][1], o.z, o.w);
            o.x += bv.x + rv.x; o.y += bv.y + rv.y;
            o.z += bv.z + rv.z; o.w += bv.w + rv.w;
            *(float4*)&Os[r*132 + tx*4] = o;
        }
    }
    __syncthreads();
    #pragma unroll
    for (int q = 0; q < 2; q++) {
        int r = ty + 8*q;
        float v[4];
        #pragma unroll
        for (int c4 = 0; c4 < 4; c4++) v[c4] = Os[r*132 + tx + 32*c4];
        float s = v[0] + v[1] + v[2] + v[3];
        s = warpSum(s);
        float mean = s * 0.0078125f;
        float vs = 0.f;
        #pragma unroll
        for (int c4 = 0; c4 < 4; c4++) { float d = v[c4] - mean; vs += d*d; }
        vs = warpSum(vs);
        float rs = rsqrtf(vs * 0.0078125f + 1e-5f);
        #pragma unroll
        for (int c4 = 0; c4 < 4; c4++) {
            int c = tx + 32*c4;
            Os[r*132 + c] = (v[c4] - mean)*rs*lng[c] + lnb[c];
        }
    }
    __syncthreads();

    #pragma unroll
    for (int q = 0; q < 2; q++){ acc[q][0] = 0ull; acc[q][1] = 0ull; }
    for (int k0 = 0; k0 < 128; k0 += 32) {
        #pragma unroll
        for (int iL = 0; iL < 16; iL++) {
            int idx = tid + 256*iL;
            int c = idx >> 5, kk = idx & 31;
            Wt[kk*132 + c] = Wv[c*128 + k0 + kk];
        }
        __syncthreads();
        #pragma unroll
        for (int kk = 0; kk < 32; kk++) {
            ulonglong2 wv = *(const ulonglong2*)&Wt[kk*132 + tx*4];
            #pragma unroll
            for (int q = 0; q < 2; q++) {
                float xv = Os[(ty + 8*q)*132 + k0 + kk];
                u64 xx = pk2(xv, xv);
                fma2(acc[q][0], xx, wv.x);
                fma2(acc[q][1], xx, wv.y);
            }
        }
        __syncthreads();
    }
    {
        float4 bv = *(const float4*)&bv4[tx*4];
        #pragma unroll
        for (int q = 0; q < 2; q++) {
            int grow = row0 + ty + 8*q;
            float4 o;
            upk2(acc[q][0], o.x, o.y);
            upk2(acc[q][1], o.z, o.w);
            o.x += bv.x; o.y += bv.y; o.z += bv.z; o.w += bv.w;
            *(float4*)&g_V4[(size_t)grow*128 + tx*4] = o;
        }
    }
}

// ---------- final z GEMM + LN + scatter ----------
__global__ __launch_bounds__(256) void zgemm_kernel(const float* __restrict__ W,
                                                    const float* __restrict__ bias,
                                                    float* __restrict__ out,
                                                    const float* __restrict__ know,
                                                    const float* __restrict__ lng,
                                                    const float* __restrict__ lnb){
    __shared__ __align__(16) float Wt[32*132];
    __shared__ float Xs[32*33];
    __shared__ __align__(16) float Os[32*132];
    int row0 = blockIdx.x * 32;
    int tid = threadIdx.x, tx = tid & 31, ty = tid >> 5;

    u64 acc[4][2];
    #pragma unroll
    for (int q = 0; q < 4; q++){ acc[q][0] = 0ull; acc[q][1] = 0ull; }
    for (int k0 = 0; k0 < 128; k0 += 32) {
        #pragma unroll
        for (int iL = 0; iL < 16; iL++) {
            int idx = tid + 256*iL;
            int c = idx >> 5, kk = idx & 31;
            Wt[kk*132 + c] = W[c*128 + k0 + kk];
        }
        #pragma unroll
        for (int iL = 0; iL < 4; iL++) {
            int idx = tid + 256*iL;
            int r = idx >> 5, kk = idx & 31;
            Xs[r*33 + kk] = g_O4[(size_t)(row0 + r)*128 + k0 + kk];
        }
        __syncthreads();
        #pragma unroll
        for (int kk = 0; kk < 32; kk++) {
            ulonglong2 wv = *(const ulonglong2*)&Wt[kk*132 + tx*4];
            #pragma unroll
            for (int q = 0; q < 4; q++) {
                float xv = Xs[(ty + 8*q)*33 + kk];
                u64 xx = pk2(xv, xv);
                fma2(acc[q][0], xx, wv.x);
                fma2(acc[q][1], xx, wv.y);
            }
        }
        __syncthreads();
    }
    {
        float4 bv = *(const float4*)&bias[tx*4];
        #pragma unroll
        for (int q = 0; q < 4; q++) {
            int r = ty + 8*q;
            int grow = row0 + r;
            int nn = (grow >> 8) & 15;
            float4 rv = *(const float4*)&know[nn*128 + tx*4];
            float4 o;
            upk2(acc[q][0], o.x, o.y);
            upk2(acc[q][1], o.z, o.w);
            o.x += bv.x + rv.x; o.y += bv.y + rv.y;
            o.z += bv.z + rv.z; o.w += bv.w + rv.w;
            *(float4*)&Os[r*132 + tx*4] = o;
        }
    }
    __syncthreads();
    #pragma unroll
    for (int q = 0; q < 4; q++) {
        int r = ty + 8*q;
        int grow = row0 + r;
        float v[4];
        #pragma unroll
        for (int c4 = 0; c4 < 4; c4++) v[c4] = Os[r*132 + tx + 32*c4];
        float s = v[0] + v[1] + v[2] + v[3];
        s = warpSum(s);
        float mean = s * 0.0078125f;
        float vs = 0.f;
        #pragma unroll
        for (int c4 = 0; c4 < 4; c4++) { float d = v[c4] - mean; vs += d*d; }
        vs = warpSum(vs);
        float rs = rsqrtf(vs * 0.0078125f + 1e-5f);
        int bb = grow >> 12, nn = (grow >> 8) & 15, ii = grow & 255;
        size_t ob = ((size_t)(bb*256 + ii))*2048 + (size_t)nn*128;
        #pragma unroll
        for (int c4 = 0; c4 < 4; c4++) {
            int c = tx + 32*c4;
            out[ob + c] = (v[c4] - mean)*rs*lng[c] + lnb[c];
        }
    }
}

// ---------- block1 attention (causal incl diag, kq_same, no maxout); grid (16,8,4) ----------
__global__ __launch_bounds__(256) void attn1_kernel(const float* __restrict__ gamma,
                                                    float* __restrict__ qs){
    __shared__ float4 Ks[256*5];   // 80B pitch -> conflict-free float4
    __shared__ float4 Vs[256*5];
    int bx = blockIdx.x;
    int split = bx & 7, sbit = bx >> 3;
    int h = blockIdx.y, b = blockIdx.z;
    int tid = threadIdx.x, lane = tid & 31, w = tid >> 5;

    const float4* qg = (const float4*)(g_Q1 + (size_t)b*32768) + h*4;
    const float4* vg = (const float4*)(g_V1 + (size_t)b*32768) + h*4;
    #pragma unroll
    for (int d4 = 0; d4 < 4; d4++) {
        Ks[tid*5 + d4] = qg[(size_t)tid*32 + d4];
        Vs[tid*5 + d4] = vg[(size_t)tid*32 + d4];
    }
    __syncthreads();
    float ag = fabsf(gamma[h]);

    for (int t = 0; t < 2; t++) {
        int i = split + 8*w + 64*(sbit + 2*t);   // bijective over 0..255 across (split,w,sbit,t)
        int cmax = (i >> 5) + 1;
        float4 q0 = Ks[i*5+0], q1 = Ks[i*5+1], q2 = Ks[i*5+2], q3 = Ks[i*5+3];

        float raw[8], mxv = -FLT_MAX;
        #pragma unroll
        for (int c = 0; c < 8; c++) {
            raw[c] = -FLT_MAX;
            if (c < cmax) {
                int j = lane + 32*c;
                if (j <= i)
                    raw[c] = 0.25f * dot16(q0,q1,q2,q3, Ks[j*5+0],Ks[j*5+1],Ks[j*5+2],Ks[j*5+3]);
                mxv = fmaxf(mxv, raw[c]);
            }
        }
        mxv = warpMax(mxv);

        float pref[8]; float base = 0.f;
        #pragma unroll
        for (int c = 0; c < 8; c++) {
            pref[c] = 0.f;
            if (c < cmax) {
                int j = lane + 32*c;
                float ev = (j <= i) ? __expf(raw[c] - mxv) : 0.f;
                float x = warpInclScan(ev, lane);
                pref[c] = base + x;
                base += __shfl_sync(FULLMASK, x, 31);
            }
        }
        float invT = 1.f / base;

        float M = fmaxf(mxv, 0.f);
        float e2[8], sm = 0.f;
        u64 r2[8];
        #pragma unroll
        for (int d = 0; d < 8; d++) r2[d] = 0ull;
        #pragma unroll
        for (int c = 0; c < 8; c++) {
            e2[c] = 0.f;
            if (c < cmax) {
                int j = lane + 32*c;
                float e = 0.f;
                if (j <= i) {
                    float delta = fmaxf(1.f - pref[c]*invT, 0.f);
                    float dist = fast_sqrt(delta * (float)(i - j));
                    float eff = fmaxf(__expf(-ag*dist), 1e-5f);
                    e = __expf(raw[c]*eff - M);
                }
                e2[c] = e;
                sm += e;
                u64 ee = pk2(e, e);
                const ulonglong2* vp = (const ulonglong2*)&Vs[j*5];
                ulonglong2 p0 = vp[0], p1 = vp[1], p2 = vp[2], p3 = vp[3];
                fma2(r2[0], ee, p0.x); fma2(r2[1], ee, p0.y);
                fma2(r2[2], ee, p1.x); fma2(r2[3], ee, p1.y);
                fma2(r2[4], ee, p2.x); fma2(r2[5], ee, p2.y);
                fma2(r2[6], ee, p3.x); fma2(r2[7], ee, p3.y);
            }
        }
        sm = warpSum(sm);
        float inv2 = 1.f / sm;

        float* qrow = qs + (((size_t)((b*8 + h)*256 + i)) << 8);
        #pragma unroll
        for (int c = 0; c < 8; c++) qrow[lane + 32*c] = e2[c]*inv2;

        float r[16];
        #pragma unroll
        for (int d = 0; d < 8; d++) upk2(r2[d], r[2*d], r[2*d+1]);
        float o = foldReduce16(r, lane) * inv2;
        if (lane < 16)
            g_O1[((size_t)(b*256 + i))*128 + h*16 + lane] = o;
    }
}

// ---------- block4 attention: fused scores + AV (R8 design + I2F hoist) ----------
__global__ __launch_bounds__(256) void attn4_kernel(const float* __restrict__ gamma,
                                                    float* __restrict__ ks){
    __shared__ float2 rp_s[256];          // {raw, pref}
    __shared__ float4 Vs[256*5];          // 80B pitch -> conflict-free
    __shared__ float red[8], tot[8];
    int g = blockIdx.x;
    int s = g & 1;
    int gh = g >> 1;
    int b = gh >> 7, n = (gh >> 3) & 15, h = gh & 7;
    int tid = threadIdx.x, lane = tid & 31, w = tid >> 5;
    int j = tid;

    const float4* qv = (const float4*)(g_Q4 + n*128 + h*16);
    const float4* kv = (const float4*)(g_K4 + ((size_t)(b*256 + j))*128 + h*16);
    float raw = 0.25f * dot16(qv[0],qv[1],qv[2],qv[3], kv[0],kv[1],kv[2],kv[3]);
    float m = warpMax(raw);
    if (lane == 0) red[w] = m;
    const float4* vv = (const float4*)(g_V4 + ((size_t)(b*256 + j))*128 + h*16);
    float4 v0 = vv[0], v1 = vv[1], v2 = vv[2], v3 = vv[3];
    __syncthreads();
    float mx = red[0];
    #pragma unroll
    for (int k2 = 1; k2 < 8; k2++) mx = fmaxf(mx, red[k2]);
    float x = warpInclScan(__expf(raw - mx), lane);
    if (lane == 31) tot[w] = x;
    __syncthreads();
    float off = 0.f;
    #pragma unroll
    for (int k2 = 0; k2 < 8; k2++) if (k2 < w) off += tot[k2];
    rp_s[j] = make_float2(raw, x + off);
    Vs[j*5+0] = v0; Vs[j*5+1] = v1; Vs[j*5+2] = v2; Vs[j*5+3] = v3;
    __syncthreads();

    float ag = fabsf(gamma[h]);
    float M = fmaxf(mx, 0.f);     // upper bound for raw*eff over ALL j (eff<=1)

    // precompute per-lane float j values (kills per-element I2F)
    float fjj[8];
    #pragma unroll
    for (int c = 0; c < 8; c++) fjj[c] = (float)(lane + 32*c);

    for (int t = 0; t < 16; t++) {
        int i = w + 16*t + 8*s;   // bijective over 0..255 across (w,t,s)
        float* krow = ks + (((size_t)((b*8 + h)*4096 + i*16 + n)) << 8);
        if (i == 0) {
            #pragma unroll
            for (int c = 0; c < 8; c++) krow[lane + 32*c] = 0.f;
            if (lane < 16)
                g_O4[((size_t)(b*16 + n)*256)*128 + h*16 + lane] = 0.f;
            continue;
        }
        float invT = 1.f / rp_s[i-1].y;
        float fi = (float)i;
        int cmax = (i + 31) >> 5;

        float e2[8], sm = 0.f, emax = 0.f;
        u64 r2[8];
        #pragma unroll
        for (int d = 0; d < 8; d++) r2[d] = 0ull;
        #pragma unroll
        for (int c = 0; c < 8; c++) {
            e2[c] = 0.f;
            if (c < cmax) {
                int jj = lane + 32*c;
                float e = 0.f;
                if (jj < i) {
                    float2 rpv = rp_s[jj];
                    float delta = fmaxf(1.f - rpv.y*invT, 0.f);
                    float dist = fast_sqrt(delta * (fi - fjj[c]));
                    float eff = fmaxf(__expf(-ag*dist), 1e-5f);
                    e = __expf(rpv.x*eff - M);
                }
                e2[c] = e;
                sm += e;
                emax = fmaxf(emax, e);
                u64 ee = pk2(e, e);
                const ulonglong2* vp = (const ulonglong2*)&Vs[jj*5];
                ulonglong2 p0 = vp[0], p1 = vp[1], p2 = vp[2], p3 = vp[3];
                fma2(r2[0], ee, p0.x); fma2(r2[1], ee, p0.y);
                fma2(r2[2], ee, p1.x); fma2(r2[3], ee, p1.y);
                fma2(r2[4], ee, p2.x); fma2(r2[5], ee, p2.y);
                fma2(r2[6], ee, p3.x); fma2(r2[7], ee, p3.y);
            }
        }
        sm = warpSum(sm);
        emax = warpMax(emax);
        float sos = fminf(1.f/emax, 5.f/sm);   // maxout scale / softmax denom

        #pragma unroll
        for (int c = 0; c < 8; c++) krow[lane + 32*c] = e2[c]*sos;

        float r[16];
        #pragma unroll
        for (int d = 0; d < 8; d++) upk2(r2[d], r[2*d], r[2*d+1]);
        float o = foldReduce16(r, lane) * sos;
        if (lane < 16)
            g_O4[((size_t)(b*16 + n)*256 + i)*128 + h*16 + lane] = o;
    }
}

extern "C" void kernel_launch(void* const* d_in, const int* in_sizes, int n_in,
                              void* d_out, int out_size){
    const float* q_emb   = (const float*)d_in[0];
    const float* s_emb   = (const float*)d_in[1];
    const float* b1_Wq   = (const float*)d_in[3];
    const float* b1_bq   = (const float*)d_in[4];
    const float* b1_Wv   = (const float*)d_in[5];
    const float* b1_bv   = (const float*)d_in[6];
    const float* b1_Wo   = (const float*)d_in[7];
    const float* b1_bo   = (const float*)d_in[8];
    const float* b1_gamma= (const float*)d_in[9];
    const float* b1_lng  = (const float*)d_in[10];
    const float* b1_lnb  = (const float*)d_in[11];
    const float* b4_Wq   = (const float*)d_in[12];
    const float* b4_bq   = (const float*)d_in[13];
    const float* b4_Wk   = (const float*)d_in[14];
    const float* b4_bk   = (const float*)d_in[15];
    const float* b4_Wv   = (const float*)d_in[16];
    const float* b4_bv   = (const float*)d_in[17];
    const float* b4_Wo   = (const float*)d_in[18];
    const float* b4_bo   = (const float*)d_in[19];
    const float* b4_gamma= (const float*)d_in[20];
    const float* b4_lng  = (const float*)d_in[21];
    const float* b4_lnb  = (const float*)d_in[22];
    const float* know    = (const float*)d_in[23];

    float* z   = (float*)d_out;              // 4*256*2048
    float* qsc = z + 2097152;                // 4*8*256*256
    float* ksc = z + 4194304;                // 4*8*256*16*256

    proj_kernel<<<193, 256>>>(q_emb, s_emb, know,
                              b1_Wq, b1_bq, b1_Wv, b1_bv,
                              b4_Wk, b4_bk, b4_Wq, b4_bq);
    attn1_kernel<<<dim3(16,8,4), 256>>>(b1_gamma, qsc);
    pv_kernel<<<64, 256>>>(q_emb, b1_Wo, b1_bo, b1_lng, b1_lnb, b4_Wv, b4_bv);
    attn4_kernel<<<1024, 256>>>(b4_gamma, ksc);
    zgemm_kernel<<<512, 256>>>(b4_Wo, b4_bo, z, know, b4_lng, b4_lnb);
}

// round 14
// speedup vs baseline: 1.2729x; 1.0435x over previous
#include <cuda_runtime.h>
#include <math.h>
#include <float.h>

typedef unsigned long long u64;
#define FULLMASK 0xFFFFFFFFu

// ---------- scratch (no allocations allowed) ----------
__device__ __align__(16) float g_Q1[1024*128];
__device__ __align__(16) float g_V1[1024*128];
__device__ __align__(16) float g_O1[1024*128];
__device__ __align__(16) float g_K4[1024*128];
__device__ __align__(16) float g_V4[1024*128];
__device__ __align__(16) float g_Q4[16*128];
__device__ __align__(16) float g_O4[16384*128];

// ---------- f32x2 packed math ----------
__device__ __forceinline__ u64 pk2(float lo, float hi){
    u64 r; asm("mov.b64 %0, {%1,%2};" : "=l"(r) : "f"(lo), "f"(hi)); return r;
}
__device__ __forceinline__ void upk2(u64 v, float& lo, float& hi){
    asm("mov.b64 {%0,%1}, %2;" : "=f"(lo), "=f"(hi) : "l"(v));
}
__device__ __forceinline__ void fma2(u64& d, u64 a, u64 b){
    asm("fma.rn.f32x2 %0, %1, %2, %0;" : "+l"(d) : "l"(a), "l"(b));
}

// ---------- helpers ----------
__device__ __forceinline__ float warpMax(float v){
    #pragma unroll
    for (int o = 16; o; o >>= 1) v = fmaxf(v, __shfl_xor_sync(FULLMASK, v, o));
    return v;
}
__device__ __forceinline__ float warpSum(float v){
    #pragma unroll
    for (int o = 16; o; o >>= 1) v += __shfl_xor_sync(FULLMASK, v, o);
    return v;
}
__device__ __forceinline__ float halfSum(float v){
    #pragma unroll
    for (int o = 8; o; o >>= 1) v += __shfl_xor_sync(FULLMASK, v, o);
    return v;
}
__device__ __forceinline__ float halfMax(float v){
    #pragma unroll
    for (int o = 8; o; o >>= 1) v = fmaxf(v, __shfl_xor_sync(FULLMASK, v, o));
    return v;
}
__device__ __forceinline__ float warpInclScan(float x, int lane){
    #pragma unroll
    for (int o = 1; o < 32; o <<= 1) {
        float y = __shfl_up_sync(FULLMASK, x, o);
        if (lane >= o) x += y;
    }
    return x;
}
__device__ __forceinline__ float fast_sqrt(float x){
    float r; asm("sqrt.approx.f32 %0, %1;" : "=f"(r) : "f"(x)); return r;
}
__device__ __forceinline__ float dot16(const float4 a0, const float4 a1, const float4 a2, const float4 a3,
                                       const float4 b0, const float4 b1, const float4 b2, const float4 b3){
    float s;
    s  = a0.x*b0.x + a0.y*b0.y + a0.z*b0.z + a0.w*b0.w;
    s += a1.x*b1.x + a1.y*b1.y + a1.z*b1.z + a1.w*b1.w;
    s += a2.x*b2.x + a2.y*b2.y + a2.z*b2.z + a2.w*b2.w;
    s += a3.x*b3.x + a3.y*b3.y + a3.z*b3.z + a3.w*b3.w;
    return s;
}
// Reduce 16 accumulators across 32 lanes; lane l gets sum over lanes of r[l&15].
__device__ __forceinline__ float foldReduce16(float r[16], int lane){
    #pragma unroll
    for (int d = 0; d < 16; d++) r[d] += __shfl_xor_sync(FULLMASK, r[d], 16);
    #pragma unroll
    for (int d = 0; d < 8; d++) {
        float x = (lane & 8) ? r[d] : r[d+8];
        float y = __shfl_xor_sync(FULLMASK, x, 8);
        r[d] = ((lane & 8) ? r[d+8] : r[d]) + y;
    }
    #pragma unroll
    for (int d = 0; d < 4; d++) {
        float x = (lane & 4) ? r[d] : r[d+4];
        float y = __shfl_xor_sync(FULLMASK, x, 4);
        r[d] = ((lane & 4) ? r[d+4] : r[d]) + y;
    }
    #pragma unroll
    for (int d = 0; d < 2; d++) {
        float x = (lane & 2) ? r[d] : r[d+2];
        float y = __shfl_xor_sync(FULLMASK, x, 2);
        r[d] = ((lane & 2) ? r[d+2] : r[d]) + y;
    }
    float x = (lane & 1) ? r[0] : r[1];
    float y = __shfl_xor_sync(FULLMASK, x, 1);
    return ((lane & 1) ? r[1] : r[0]) + y;
}
// Fold 16 accumulators within each 16-lane half; lane l gets half-sum of r[l&15].
__device__ __forceinline__ float foldReduceHalf16(float r[16], int lane){
    #pragma unroll
    for (int d = 0; d < 8; d++) {
        float x = (lane & 8) ? r[d] : r[d+8];
        float y = __shfl_xor_sync(FULLMASK, x, 8);
        r[d] = ((lane & 8) ? r[d+8] : r[d]) + y;
    }
    #pragma unroll
    for (int d = 0; d < 4; d++) {
        float x = (lane & 4) ? r[d] : r[d+4];
        float y = __shfl_xor_sync(FULLMASK, x, 4);
        r[d] = ((lane & 4) ? r[d+4] : r[d]) + y;
    }
    #pragma unroll
    for (int d = 0; d < 2; d++) {
        float x = (lane & 2) ? r[d] : r[d+2];
        float y = __shfl_xor_sync(FULLMASK, x, 2);
        r[d] = ((lane & 2) ? r[d+2] : r[d]) + y;
    }
    float x = (lane & 1) ? r[0] : r[1];
    float y = __shfl_xor_sync(FULLMASK, x, 1);
    return ((lane & 1) ? r[1] : r[0]) + y;
}

// ---------- GEMM core 16-row tile: out[row0..row0+15] = X@W^T + bias ----------
__device__ __forceinline__ void gemm_core16(const float* __restrict__ X, const float* __restrict__ W,
                                            const float* __restrict__ bias, float* __restrict__ out,
                                            int M, int row0, float* Wt, float* Xs){
    int tid = threadIdx.x, tx = tid & 31, ty = tid >> 5;
    u64 acc[2][2];
    #pragma unroll
    for (int q = 0; q < 2; q++){ acc[q][0] = 0ull; acc[q][1] = 0ull; }

    for (int k0 = 0; k0 < 128; k0 += 32) {
        #pragma unroll
        for (int iL = 0; iL < 16; iL++) {
            int idx = tid + 256*iL;
            int c = idx >> 5, kk = idx & 31;
            Wt[kk*132 + c] = W[c*128 + k0 + kk];
        }
        #pragma unroll
        for (int iL = 0; iL < 2; iL++) {
            int idx = tid + 256*iL;
            int r = idx >> 5, kk = idx & 31;
            int grow = row0 + r;
            Xs[r*33 + kk] = (grow < M) ? X[(size_t)grow*128 + k0 + kk] : 0.f;
        }
        __syncthreads();
        #pragma unroll
        for (int kk = 0; kk < 32; kk++) {
            ulonglong2 wv = *(const ulonglong2*)&Wt[kk*132 + tx*4];
            #pragma unroll
            for (int q = 0; q < 2; q++) {
                float xv = Xs[(ty + 8*q)*33 + kk];
                u64 xx = pk2(xv, xv);
                fma2(acc[q][0], xx, wv.x);
                fma2(acc[q][1], xx, wv.y);
            }
        }
        __syncthreads();
    }
    float4 bv = *(const float4*)&bias[tx*4];
    #pragma unroll
    for (int q = 0; q < 2; q++) {
        int grow = row0 + ty + 8*q;
        if (grow < M) {
            float4 o;
            upk2(acc[q][0], o.x, o.y);
            upk2(acc[q][1], o.z, o.w);
            o.x += bv.x; o.y += bv.y; o.z += bv.z; o.w += bv.w;
            *(float4*)&out[(size_t)grow*128 + tx*4] = o;
        }
    }
}

// ---------- fused projections: Q1 | V1 | K4 | Q4, 16-row tiles (193 blocks) ----------
__global__ __launch_bounds__(256) void proj_kernel(const float* __restrict__ q_emb,
                                                   const float* __restrict__ s_emb,
                                                   const float* __restrict__ know,
                                                   const float* __restrict__ Wq1, const float* __restrict__ bq1,
                                                   const float* __restrict__ Wv1, const float* __restrict__ bv1,
                                                   const float* __restrict__ Wk4, const float* __restrict__ bk4,
                                                   const float* __restrict__ Wq4, const float* __restrict__ bq4){
    __shared__ __align__(16) float Wt[32*132];
    __shared__ float Xs[16*33];
    int bx = blockIdx.x;
    const float *X, *W, *bias; float* out; int M, row0;
    if (bx < 64)       { X=q_emb; W=Wq1; bias=bq1; out=g_Q1; M=1024; row0=bx*16; }
    else if (bx < 128) { X=s_emb; W=Wv1; bias=bv1; out=g_V1; M=1024; row0=(bx-64)*16; }
    else if (bx < 192) { X=q_emb; W=Wk4; bias=bk4; out=g_K4; M=1024; row0=(bx-128)*16; }
    else               { X=know;  W=Wq4; bias=bq4; out=g_Q4; M=16;   row0=0; }
    gemm_core16(X, W, bias, out, M, row0, Wt, Xs);
}

// ---------- fused P+V4 (16-row tiles): V4 = LN(O1@Wo + b + q_emb) @ Wv^T + bv ----------
__global__ __launch_bounds__(256) void pv_kernel(const float* __restrict__ q_emb,
                                                 const float* __restrict__ Wo, const float* __restrict__ bo,
                                                 const float* __restrict__ lng, const float* __restrict__ lnb,
                                                 const float* __restrict__ Wv, const float* __restrict__ bv4){
    __shared__ __align__(16) float Wt[32*132];
    __shared__ float Xs[16*33];
    __shared__ __align__(16) float Os[16*132];
    int row0 = blockIdx.x * 16;
    int tid = threadIdx.x, tx = tid & 31, ty = tid >> 5;

    u64 acc[2][2];
    #pragma unroll
    for (int q = 0; q < 2; q++){ acc[q][0] = 0ull; acc[q][1] = 0ull; }
    for (int k0 = 0; k0 < 128; k0 += 32) {
        #pragma unroll
        for (int iL = 0; iL < 16; iL++) {
            int idx = tid + 256*iL;
            int c = idx >> 5, kk = idx & 31;
            Wt[kk*132 + c] = Wo[c*128 + k0 + kk];
        }
        #pragma unroll
        for (int iL = 0; iL < 2; iL++) {
            int idx = tid + 256*iL;
            int r = idx >> 5, kk = idx & 31;
            Xs[r*33 + kk] = g_O1[(size_t)(row0 + r)*128 + k0 + kk];
        }
        __syncthreads();
        #pragma unroll
        for (int kk = 0; kk < 32; kk++) {
            ulonglong2 wv = *(const ulonglong2*)&Wt[kk*132 + tx*4];
            #pragma unroll
            for (int q = 0; q < 2; q++) {
                float xv = Xs[(ty + 8*q)*33 + kk];
                u64 xx = pk2(xv, xv);
                fma2(acc[q][0], xx, wv.x);
                fma2(acc[q][1], xx, wv.y);
            }
        }
        __syncthreads();
    }
    {
        float4 bv = *(const float4*)&bo[tx*4];
        #pragma unroll
        for (int q = 0; q < 2; q++) {
            int r = ty + 8*q;
            float4 rv = *(const float4*)&q_emb[(size_t)(row0 + r)*128 + tx*4];
            float4 o;
            upk2(acc[q][0], o.x, o.y);
            upk2(acc[q][1], o.z, o.w);
            o.x += bv.x + rv.x; o.y += bv.y + rv.y;
            o.z += bv.z + rv.z; o.w += bv.w + rv.w;
            *(float4*)&Os[r*132 + tx*4] = o;
        }
    }
    __syncthreads();
    #pragma unroll
    for (int q = 0; q < 2; q++) {
        int r = ty + 8*q;
        float v[4];
        #pragma unroll
        for (int c4 = 0; c4 < 4; c4++) v[c4] = Os[r*132 + tx + 32*c4];
        float s = v[0] + v[1] + v[2] + v[3];
        s = warpSum(s);
        float mean = s * 0.0078125f;
        float vs = 0.f;
        #pragma unroll
        for (int c4 = 0; c4 < 4; c4++) { float d = v[c4] - mean; vs += d*d; }
        vs = warpSum(vs);
        float rs = rsqrtf(vs * 0.0078125f + 1e-5f);
        #pragma unroll
        for (int c4 = 0; c4 < 4; c4++) {
            int c = tx + 32*c4;
            Os[r*132 + c] = (v[c4] - mean)*rs*lng[c] + lnb[c];
        }
    }
    __syncthreads();

    #pragma unroll
    for (int q = 0; q < 2; q++){ acc[q][0] = 0ull; acc[q][1] = 0ull; }
    for (int k0 = 0; k0 < 128; k0 += 32) {
        #pragma unroll
        for (int iL = 0; iL < 16; iL++) {
            int idx = tid + 256*iL;
            int c = idx >> 5, kk = idx & 31;
            Wt[kk*132 + c] = Wv[c*128 + k0 + kk];
        }
        __syncthreads();
        #pragma unroll
        for (int kk = 0; kk < 32; kk++) {
            ulonglong2 wv = *(const ulonglong2*)&Wt[kk*132 + tx*4];
            #pragma unroll
            for (int q = 0; q < 2; q++) {
                float xv = Os[(ty + 8*q)*132 + k0 + kk];
                u64 xx = pk2(xv, xv);
                fma2(acc[q][0], xx, wv.x);
                fma2(acc[q][1], xx, wv.y);
            }
        }
        __syncthreads();
    }
    {
        float4 bv = *(const float4*)&bv4[tx*4];
        #pragma unroll
        for (int q = 0; q < 2; q++) {
            int grow = row0 + ty + 8*q;
            float4 o;
            upk2(acc[q][0], o.x, o.y);
            upk2(acc[q][1], o.z, o.w);
            o.x += bv.x; o.y += bv.y; o.z += bv.z; o.w += bv.w;
            *(float4*)&g_V4[(size_t)grow*128 + tx*4] = o;
        }
    }
}

// ---------- final z GEMM + LN + scatter ----------
__global__ __launch_bounds__(256) void zgemm_kernel(const float* __restrict__ W,
                                                    const float* __restrict__ bias,
                                                    float* __restrict__ out,
                                                    const float* __restrict__ know,
                                                    const float* __restrict__ lng,
                                                    const float* __restrict__ lnb){
    __shared__ __align__(16) float Wt[32*132];
    __shared__ float Xs[32*33];
    __shared__ __align__(16) float Os[32*132];
    int row0 = blockIdx.x * 32;
    int tid = threadIdx.x, tx = tid & 31, ty = tid >> 5;

    u64 acc[4][2];
    #pragma unroll
    for (int q = 0; q < 4; q++){ acc[q][0] = 0ull; acc[q][1] = 0ull; }
    for (int k0 = 0; k0 < 128; k0 += 32) {
        #pragma unroll
        for (int iL = 0; iL < 16; iL++) {
            int idx = tid + 256*iL;
            int c = idx >> 5, kk = idx & 31;
            Wt[kk*132 + c] = W[c*128 + k0 + kk];
        }
        #pragma unroll
        for (int iL = 0; iL < 4; iL++) {
            int idx = tid + 256*iL;
            int r = idx >> 5, kk = idx & 31;
            Xs[r*33 + kk] = g_O4[(size_t)(row0 + r)*128 + k0 + kk];
        }
        __syncthreads();
        #pragma unroll
        for (int kk = 0; kk < 32; kk++) {
            ulonglong2 wv = *(const ulonglong2*)&Wt[kk*132 + tx*4];
            #pragma unroll
            for (int q = 0; q < 4; q++) {
                float xv = Xs[(ty + 8*q)*33 + kk];
                u64 xx = pk2(xv, xv);
                fma2(acc[q][0], xx, wv.x);
                fma2(acc[q][1], xx, wv.y);
            }
        }
        __syncthreads();
    }
    {
        float4 bv = *(const float4*)&bias[tx*4];
        #pragma unroll
        for (int q = 0; q < 4; q++) {
            int r = ty + 8*q;
            int grow = row0 + r;
            int nn = (grow >> 8) & 15;
            float4 rv = *(const float4*)&know[nn*128 + tx*4];
            float4 o;
            upk2(acc[q][0], o.x, o.y);
            upk2(acc[q][1], o.z, o.w);
            o.x += bv.x + rv.x; o.y += bv.y + rv.y;
            o.z += bv.z + rv.z; o.w += bv.w + rv.w;
            *(float4*)&Os[r*132 + tx*4] = o;
        }
    }
    __syncthreads();
    #pragma unroll
    for (int q = 0; q < 4; q++) {
        int r = ty + 8*q;
        int grow = row0 + r;
        float v[4];
        #pragma unroll
        for (int c4 = 0; c4 < 4; c4++) v[c4] = Os[r*132 + tx + 32*c4];
        float s = v[0] + v[1] + v[2] + v[3];
        s = warpSum(s);
        float mean = s * 0.0078125f;
        float vs = 0.f;
        #pragma unroll
        for (int c4 = 0; c4 < 4; c4++) { float d = v[c4] - mean; vs += d*d; }
        vs = warpSum(vs);
        float rs = rsqrtf(vs * 0.0078125f + 1e-5f);
        int bb = grow >> 12, nn = (grow >> 8) & 15, ii = grow & 255;
        size_t ob = ((size_t)(bb*256 + ii))*2048 + (size_t)nn*128;
        #pragma unroll
        for (int c4 = 0; c4 < 4; c4++) {
            int c = tx + 32*c4;
            out[ob + c] = (v[c4] - mean)*rs*lng[c] + lnb[c];
        }
    }
}

// ---------- block1 attention (causal incl diag, kq_same, no maxout); grid (16,8,4) ----------
__global__ __launch_bounds__(256) void attn1_kernel(const float* __restrict__ gamma,
                                                    float* __restrict__ qs){
    __shared__ float4 Ks[256*5];   // 80B pitch -> conflict-free float4
    __shared__ float4 Vs[256*5];
    int bx = blockIdx.x;
    int split = bx & 7, sbit = bx >> 3;
    int h = blockIdx.y, b = blockIdx.z;
    int tid = threadIdx.x, lane = tid & 31, w = tid >> 5;

    const float4* qg = (const float4*)(g_Q1 + (size_t)b*32768) + h*4;
    const float4* vg = (const float4*)(g_V1 + (size_t)b*32768) + h*4;
    #pragma unroll
    for (int d4 = 0; d4 < 4; d4++) {
        Ks[tid*5 + d4] = qg[(size_t)tid*32 + d4];
        Vs[tid*5 + d4] = vg[(size_t)tid*32 + d4];
    }
    __syncthreads();
    float ag = fabsf(gamma[h]);

    for (int t = 0; t < 2; t++) {
        int i = split + 8*w + 64*(sbit + 2*t);   // bijective over 0..255
        int cmax = (i >> 5) + 1;
        float4 q0 = Ks[i*5+0], q1 = Ks[i*5+1], q2 = Ks[i*5+2], q3 = Ks[i*5+3];

        float raw[8], mxv = -FLT_MAX;
        #pragma unroll
        for (int c = 0; c < 8; c++) {
            raw[c] = -FLT_MAX;
            if (c < cmax) {
                int j = lane + 32*c;
                if (j <= i)
                    raw[c] = 0.25f * dot16(q0,q1,q2,q3, Ks[j*5+0],Ks[j*5+1],Ks[j*5+2],Ks[j*5+3]);
                mxv = fmaxf(mxv, raw[c]);
            }
        }
        mxv = warpMax(mxv);

        float pref[8]; float base = 0.f;
        #pragma unroll
        for (int c = 0; c < 8; c++) {
            pref[c] = 0.f;
            if (c < cmax) {
                int j = lane + 32*c;
                float ev = (j <= i) ? __expf(raw[c] - mxv) : 0.f;
                float x = warpInclScan(ev, lane);
                pref[c] = base + x;
                base += __shfl_sync(FULLMASK, x, 31);
            }
        }
        float invT = 1.f / base;

        float M = fmaxf(mxv, 0.f);
        float e2[8], sm = 0.f;
        u64 r2[8];
        #pragma unroll
        for (int d = 0; d < 8; d++) r2[d] = 0ull;
        #pragma unroll
        for (int c = 0; c < 8; c++) {
            e2[c] = 0.f;
            if (c < cmax) {
                int j = lane + 32*c;
                float e = 0.f;
                if (j <= i) {
                    float delta = fmaxf(1.f - pref[c]*invT, 0.f);
                    float dist = fast_sqrt(delta * (float)(i - j));
                    float eff = fmaxf(__expf(-ag*dist), 1e-5f);
                    e = __expf(raw[c]*eff - M);
                }
                e2[c] = e;
                sm += e;
                u64 ee = pk2(e, e);
                const ulonglong2* vp = (const ulonglong2*)&Vs[j*5];
                ulonglong2 p0 = vp[0], p1 = vp[1], p2 = vp[2], p3 = vp[3];
                fma2(r2[0], ee, p0.x); fma2(r2[1], ee, p0.y);
                fma2(r2[2], ee, p1.x); fma2(r2[3], ee, p1.y);
                fma2(r2[4], ee, p2.x); fma2(r2[5], ee, p2.y);
                fma2(r2[6], ee, p3.x); fma2(r2[7], ee, p3.y);
            }
        }
        sm = warpSum(sm);
        float inv2 = 1.f / sm;

        float* qrow = qs + (((size_t)((b*8 + h)*256 + i)) << 8);
        #pragma unroll
        for (int c = 0; c < 8; c++) qrow[lane + 32*c] = e2[c]*inv2;

        float r[16];
        #pragma unroll
        for (int d = 0; d < 8; d++) upk2(r2[d], r[2*d], r[2*d+1]);
        float o = foldReduce16(r, lane) * inv2;
        if (lane < 16)
            g_O1[((size_t)(b*256 + i))*128 + h*16 + lane] = o;
    }
}

// ---------- block4 attention: half-warp row pairing (V/rp broadcast across halves) ----------
__global__ __launch_bounds__(256) void attn4_kernel(const float* __restrict__ gamma,
                                                    float* __restrict__ ks){
    __shared__ float2 rp_s[256];          // {raw, pref}
    __shared__ float4 Vs[256*5];          // 80B pitch -> conflict-free
    __shared__ float red[8], tot[8];
    int g = blockIdx.x;
    int s = g & 1;
    int gh = g >> 1;
    int b = gh >> 7, n = (gh >> 3) & 15, h = gh & 7;
    int tid = threadIdx.x, lane = tid & 31, w = tid >> 5;
    int j = tid;

    const float4* qv = (const float4*)(g_Q4 + n*128 + h*16);
    const float4* kv = (const float4*)(g_K4 + ((size_t)(b*256 + j))*128 + h*16);
    float raw = 0.25f * dot16(qv[0],qv[1],qv[2],qv[3], kv[0],kv[1],kv[2],kv[3]);
    float m = warpMax(raw);
    if (lane == 0) red[w] = m;
    const float4* vv = (const float4*)(g_V4 + ((size_t)(b*256 + j))*128 + h*16);
    float4 v0 = vv[0], v1 = vv[1], v2 = vv[2], v3 = vv[3];
    __syncthreads();
    float mx = red[0];
    #pragma unroll
    for (int k2 = 1; k2 < 8; k2++) mx = fmaxf(mx, red[k2]);
    float x = warpInclScan(__expf(raw - mx), lane);
    if (lane == 31) tot[w] = x;
    __syncthreads();
    float off = 0.f;
    #pragma unroll
    for (int k2 = 0; k2 < 8; k2++) if (k2 < w) off += tot[k2];
    rp_s[j] = make_float2(raw, x + off);
    Vs[j*5+0] = v0; Vs[j*5+1] = v1; Vs[j*5+2] = v2; Vs[j*5+3] = v3;
    __syncthreads();

    float ag = fabsf(gamma[h]);
    float M = fmaxf(mx, 0.f);     // upper bound for raw*eff over ALL j (eff<=1)

    int hl = lane & 15;           // lane within half-warp
    // rows: half 0 of the warp handles i=2*base, half 1 handles i=2*base+1
    for (int t = 0; t < 8; t++) {
        int base = w + 8*s + 16*t;          // 0..127 bijective
        int i = 2*base + (lane >> 4);
        float* krow = ks + (((size_t)((b*8 + h)*4096 + i*16 + n)) << 8);
        float invT = (i > 0) ? 1.f / rp_s[i-1].y : 0.f;
        float fib = (float)i - (float)hl;   // fi - hl; dif = fib - 16c
        int cmax = (2*base + 16) >> 4;      // ceil((i_B)/16), warp-uniform

        float e2[16], sm = 0.f, emax = 0.f;
        u64 r2[8];
        #pragma unroll
        for (int d = 0; d < 8; d++) r2[d] = 0ull;
        #pragma unroll
        for (int c = 0; c < 16; c++) {
            e2[c] = 0.f;
            if (c < cmax) {
                int jj = hl + 16*c;
                float2 rpv = rp_s[jj];          // broadcast across the two halves
                float e = 0.f;
                if (jj < i) {
                    float delta = fmaxf(1.f - rpv.y*invT, 0.f);
                    float dist = fast_sqrt(delta * (fib - (float)(16*c)));
                    float eff = fmaxf(__expf(-ag*dist), 1e-5f);
                    e = __expf(rpv.x*eff - M);
                }
                e2[c] = e;
                sm += e;
                emax = fmaxf(emax, e);
                u64 ee = pk2(e, e);
                const ulonglong2* vp = (const ulonglong2*)&Vs[jj*5];   // broadcast
                ulonglong2 p0 = vp[0], p1 = vp[1], p2 = vp[2], p3 = vp[3];
                fma2(r2[0], ee, p0.x); fma2(r2[1], ee, p0.y);
                fma2(r2[2], ee, p1.x); fma2(r2[3], ee, p1.y);
                fma2(r2[4], ee, p2.x); fma2(r2[5], ee, p2.y);
                fma2(r2[6], ee, p3.x); fma2(r2[7], ee, p3.y);
            }
        }
        sm = halfSum(sm);
        emax = halfMax(emax);
        float sos = fminf(1.f/emax, 5.f/sm);   // maxout scale / softmax denom
        if (i == 0) sos = 0.f;                 // row 0: all-zero scores

        #pragma unroll
        for (int c = 0; c < 16; c++) krow[hl + 16*c] = e2[c]*sos;

        float r[16];
        #pragma unroll
        for (int d = 0; d < 8; d++) upk2(r2[d], r[2*d], r[2*d+1]);
        float o = foldReduceHalf16(r, lane) * sos;
        g_O4[((size_t)(b*16 + n)*256 + i)*128 + h*16 + hl] = o;
    }
}

extern "C" void kernel_launch(void* const* d_in, const int* in_sizes, int n_in,
                              void* d_out, int out_size){
    const float* q_emb   = (const float*)d_in[0];
    const float* s_emb   = (const float*)d_in[1];
    const float* b1_Wq   = (const float*)d_in[3];
    const float* b1_bq   = (const float*)d_in[4];
    const float* b1_Wv   = (const float*)d_in[5];
    const float* b1_bv   = (const float*)d_in[6];
    const float* b1_Wo   = (const float*)d_in[7];
    const float* b1_bo   = (const float*)d_in[8];
    const float* b1_gamma= (const float*)d_in[9];
    const float* b1_lng  = (const float*)d_in[10];
    const float* b1_lnb  = (const float*)d_in[11];
    const float* b4_Wq   = (const float*)d_in[12];
    const float* b4_bq   = (const float*)d_in[13];
    const float* b4_Wk   = (const float*)d_in[14];
    const float* b4_bk   = (const float*)d_in[15];
    const float* b4_Wv   = (const float*)d_in[16];
    const float* b4_bv   = (const float*)d_in[17];
    const float* b4_Wo   = (const float*)d_in[18];
    const float* b4_bo   = (const float*)d_in[19];
    const float* b4_gamma= (const float*)d_in[20];
    const float* b4_lng  = (const float*)d_in[21];
    const float* b4_lnb  = (const float*)d_in[22];
    const float* know    = (const float*)d_in[23];

    float* z   = (float*)d_out;              // 4*256*2048
    float* qsc = z + 2097152;                // 4*8*256*256
    float* ksc = z + 4194304;                // 4*8*256*16*256

    proj_kernel<<<193, 256>>>(q_emb, s_emb, know,
                              b1_Wq, b1_bq, b1_Wv, b1_bv,
                              b4_Wk, b4_bk, b4_Wq, b4_bq);
    attn1_kernel<<<dim3(16,8,4), 256>>>(b1_gamma, qsc);
    pv_kernel<<<64, 256>>>(q_emb, b1_Wo, b1_bo, b1_lng, b1_lnb, b4_Wv, b4_bv);
    attn4_kernel<<<1024, 256>>>(b4_gamma, ksc);
    zgemm_kernel<<<512, 256>>>(b4_Wo, b4_bo, z, know, b4_lng, b4_lnb);
}